// round 12
// baseline (speedup 1.0000x reference)
#include <cuda_runtime.h>
#include <math.h>

#define BB 2
#define LL 1024
#define XX 4
#define EE 128
#define YY 4
#define SCALE 0.08838834764831845f   // 1/sqrt(128)

typedef unsigned short ushort_t;

// ---------------- scratch (static device globals) --------------------------
__device__ float g_search[8*1024*1024];                 // stage1 scores fp32  32 MB
__device__ float g_s2    [2*10*1024*1024];              // stage2 scores fp32  80 MB
__device__ float g_vpart [BB*LL*EE*XX];                 // [b][l][e][x]         4 MB

__device__ __align__(16) ushort_t g_qh [2*1024*4*128], g_ql [2*1024*4*128];
__device__ __align__(16) ushort_t g_kh [2*1024*4*128], g_kl [2*1024*4*128];
__device__ __align__(16) ushort_t g_vh [2*1024*512],   g_vl [2*1024*512];
__device__ __align__(16) ushort_t g_qph[2*1024*4*128], g_qpl[2*1024*4*128];
__device__ __align__(16) ushort_t g_wkh[128*128],      g_wkl[128*128];
__device__ __align__(16) ushort_t g_sh [8*1024*1024],  g_sl [8*1024*1024];   // Search bf16
__device__ __align__(16) ushort_t g_qkh[2*1024*4*128], g_qkl[2*1024*4*128];
__device__ __align__(16) ushort_t g_rh [2*4*4*1024*128], g_rl[2*4*4*1024*128];
__device__ __align__(16) ushort_t g_s2h[2*10*1024*1024], g_s2l[2*10*1024*1024];

__constant__ int c_xy_x[10] = {0,1,1,2,2,2,3,3,3,3};
__constant__ int c_xy_y[10] = {0,0,1,0,1,2,0,1,2,3};
__constant__ int c_tri[4]  = {0,1,3,6};

// libdevice path — bit-matches jax-on-GPU reference. DO NOT CHANGE.
__device__ __forceinline__ float sig_transform(float v) {
    float t = 5.0f * v;
    float e = expf(-t);
    float sigmoid = 1.0f / (1.0f + e);
    float sg = sigmoid + 1e-5f;
    float p = powf(3.0f, sg);
    return p - 1.0f;
}

// ================= bf16 split helpers =======================================
__device__ __forceinline__ unsigned bfbits(float x) {
    unsigned u = __float_as_uint(x);
    return (u + 0x7fffu + ((u >> 16) & 1u)) >> 16;
}
__device__ __forceinline__ float bfval(unsigned b) { return __uint_as_float(b << 16); }
__device__ __forceinline__ void split_pack(float x0, float x1, unsigned &hi, unsigned &lo) {
    unsigned h0 = bfbits(x0), h1 = bfbits(x1);
    unsigned l0 = bfbits(x0 - bfval(h0)), l1 = bfbits(x1 - bfval(h1));
    hi = h0 | (h1 << 16);
    lo = l0 | (l1 << 16);
}
__device__ __forceinline__ void mma_bf16(float (&c)[4],
    unsigned a0, unsigned a1, unsigned a2, unsigned a3,
    unsigned b0, unsigned b1)
{
    asm volatile("mma.sync.aligned.m16n8k16.row.col.f32.bf16.bf16.f32 "
        "{%0,%1,%2,%3},{%4,%5,%6,%7},{%8,%9},{%0,%1,%2,%3};"
        : "+f"(c[0]), "+f"(c[1]), "+f"(c[2]), "+f"(c[3])
        : "r"(a0), "r"(a1), "r"(a2), "r"(a3), "r"(b0), "r"(b1));
}
__device__ __forceinline__ void ldsm_x4(unsigned &r0, unsigned &r1,
                                        unsigned &r2, unsigned &r3, unsigned addr)
{
    asm volatile("ldmatrix.sync.aligned.m8n8.x4.shared.b16 {%0,%1,%2,%3}, [%4];"
        : "=r"(r0), "=r"(r1), "=r"(r2), "=r"(r3) : "r"(addr));
}
__device__ __forceinline__ void ldsm_x4t(unsigned &r0, unsigned &r1,
                                         unsigned &r2, unsigned &r3, unsigned addr)
{
    asm volatile("ldmatrix.sync.aligned.m8n8.x4.trans.shared.b16 {%0,%1,%2,%3}, [%4];"
        : "=r"(r0), "=r"(r1), "=r"(r2), "=r"(r3) : "r"(addr));
}
__device__ __forceinline__ void cp_async16(void* dst, const void* src) {
    unsigned s = (unsigned)__cvta_generic_to_shared(dst);
    asm volatile("cp.async.cg.shared.global [%0], [%1], 16;" :: "r"(s), "l"(src));
}
#define CP_COMMIT() asm volatile("cp.async.commit_group;")
template<int N>
__device__ __forceinline__ void cp_wait() {
    asm volatile("cp.async.wait_group %0;" :: "n"(N));
}

// C tile 128x64, 256 threads (8 warps = 4x2 grid of 32x32 warp tiles).
// Operands pre-split bf16 hi/lo in gmem; lda/ldb in bf16 elements.
// TRANSB=0: B is [n][k] (NT). TRANSB=1: B is [k][n] (NN, via ldmatrix.trans).
// 3-stage cp.async pipeline, prefetch distance 2, ONE barrier per chunk.
// Stage s layout (words): SA_hi [0,2560) SA_lo [2560,5120) SB_hi/lo [5120,7680)
template<int TRANSB>
__device__ __forceinline__ void mma_core(
    unsigned* __restrict__ SM_,
    const ushort_t* __restrict__ Ahg, const ushort_t* __restrict__ Alg, int lda,
    const ushort_t* __restrict__ Bhg, const ushort_t* __restrict__ Blg, int ldb,
    int K, float (&acc)[2][4][4])
{
    const int tid = threadIdx.x;
    const int lane = tid & 31, w = tid >> 5;
    const int wrow = w >> 1, wcol = w & 1;
    const int lm = lane & 15, lq = lane >> 4;

    const int ar = tid >> 1, ax = tid & 1;    // A staging: 2 thr/row, 16 ushort each
    const int br = tid >> 2, bq = tid & 3;    // B NT: 4 thr/row, 8 ushort each
    const int half = tid >> 7, t7 = tid & 127;
    const int nr = t7 >> 2, nq = t7 & 3;      // B NN: per plane-half, 16 ushort each

    auto prefetch = [&](int kk, int s) {
        unsigned* SA = SM_ + s * 7680;
        unsigned* SB = SA + 5120;
        const ushort_t* pa = Ahg + (size_t)ar*lda + kk + ax*16;
        const ushort_t* pl = Alg + (size_t)ar*lda + kk + ax*16;
        cp_async16(&SA[ar*20 + ax*8],            pa);
        cp_async16(&SA[ar*20 + ax*8 + 4],        pa + 8);
        cp_async16(&SA[2560 + ar*20 + ax*8],     pl);
        cp_async16(&SA[2560 + ar*20 + ax*8 + 4], pl + 8);
        if (TRANSB) {
            const ushort_t* pb = (half ? Blg : Bhg) + (size_t)(kk + nr)*ldb + nq*16;
            ushort_t* bd = (ushort_t*)(SB + half*1280) + nr*72 + nq*16;
            cp_async16(bd,     pb);
            cp_async16(bd + 8, pb + 8);
        } else {
            cp_async16(&SB[br*20 + bq*4],        Bhg + (size_t)br*ldb + kk + bq*8);
            cp_async16(&SB[1280 + br*20 + bq*4], Blg + (size_t)br*ldb + kk + bq*8);
        }
    };

    const int nck = K >> 5;
    prefetch(0, 0); CP_COMMIT();
    if (nck > 1) { prefetch(32, 1); CP_COMMIT(); }
    for (int c = 0; c < nck; c++) {
        if (c == nck - 1) cp_wait<0>(); else cp_wait<1>();
        __syncthreads();
        unsigned* SA = SM_ + (c % 3) * 7680;
        unsigned* SB = SA + 5120;
        // prefetch chunk c+2 into stage (c+2)%3 — safe: all warps passed the
        // barrier above, so everyone finished reading stage (c-1)%3 == (c+2)%3.
        if (c + 2 < nck) { prefetch((c+2) << 5, (c+2) % 3); CP_COMMIT(); }
#pragma unroll
        for (int k16 = 0; k16 < 2; k16++) {
            const int ko = k16*8;
            unsigned ah[2][4], al[2][4], bh[4][2], bl[4][2];
#pragma unroll
            for (int mt = 0; mt < 2; mt++) {
                int m = wrow*32 + mt*16;
                unsigned aw = (unsigned)__cvta_generic_to_shared(
                    &SA[(m + lm)*20 + ko + (lq<<2)]);
                ldsm_x4(ah[mt][0], ah[mt][1], ah[mt][2], ah[mt][3], aw);
                ldsm_x4(al[mt][0], al[mt][1], al[mt][2], al[mt][3], aw + 2560*4);
            }
#pragma unroll
            for (int p = 0; p < 2; p++) {
                int n0 = wcol*32 + p*16;
                if (TRANSB) {
                    const ushort_t* bb = (const ushort_t*)SB;
                    unsigned bw = (unsigned)__cvta_generic_to_shared(
                        bb + (k16*16 + lm)*72 + n0 + (lq<<3));
                    ldsm_x4t(bh[2*p][0], bh[2*p][1], bh[2*p+1][0], bh[2*p+1][1], bw);
                    ldsm_x4t(bl[2*p][0], bl[2*p][1], bl[2*p+1][0], bl[2*p+1][1], bw + 1280*4);
                } else {
                    unsigned bw = (unsigned)__cvta_generic_to_shared(
                        &SB[(n0 + lm)*20 + ko + (lq<<2)]);
                    ldsm_x4(bh[2*p][0], bh[2*p+1][0], bh[2*p][1], bh[2*p+1][1], bw);
                    ldsm_x4(bl[2*p][0], bl[2*p+1][0], bl[2*p][1], bl[2*p+1][1], bw + 1280*4);
                }
            }
#pragma unroll
            for (int mt = 0; mt < 2; mt++)
#pragma unroll
                for (int nt = 0; nt < 4; nt++) {
                    mma_bf16(acc[mt][nt], ah[mt][0],ah[mt][1],ah[mt][2],ah[mt][3], bh[nt][0],bh[nt][1]);
                    mma_bf16(acc[mt][nt], ah[mt][0],ah[mt][1],ah[mt][2],ah[mt][3], bl[nt][0],bl[nt][1]);
                    mma_bf16(acc[mt][nt], al[mt][0],al[mt][1],al[mt][2],al[mt][3], bh[nt][0],bh[nt][1]);
                }
        }
    }
    __syncthreads();
}

#define SMEM_MMA (3*7680*4)   // 92160 bytes

__device__ __forceinline__ void epilogue_f32(
    float (&acc)[2][4][4], float* C, int ldc, float scale)
{
    const int lane = threadIdx.x & 31, w = threadIdx.x >> 5;
    const int g = lane >> 2, tg = lane & 3;
    const int wrow = w >> 1, wcol = w & 1;
#pragma unroll
    for (int mt = 0; mt < 2; mt++)
#pragma unroll
        for (int nt = 0; nt < 4; nt++) {
            int r0 = wrow*32 + mt*16 + g;
            int c0 = wcol*32 + nt*8 + 2*tg;
            float2 v0 = {acc[mt][nt][0]*scale, acc[mt][nt][1]*scale};
            float2 v1 = {acc[mt][nt][2]*scale, acc[mt][nt][3]*scale};
            *(float2*)(C + (size_t)r0*ldc + c0) = v0;
            *(float2*)(C + (size_t)(r0+8)*ldc + c0) = v1;
        }
}

__device__ __forceinline__ void epilogue_bf16(
    float (&acc)[2][4][4], ushort_t* Ch, ushort_t* Cl, int ldc)
{
    const int lane = threadIdx.x & 31, w = threadIdx.x >> 5;
    const int g = lane >> 2, tg = lane & 3;
    const int wrow = w >> 1, wcol = w & 1;
#pragma unroll
    for (int mt = 0; mt < 2; mt++)
#pragma unroll
        for (int nt = 0; nt < 4; nt++) {
            int r0 = wrow*32 + mt*16 + g;
            int c0 = wcol*32 + nt*8 + 2*tg;
            unsigned h, l;
            split_pack(acc[mt][nt][0], acc[mt][nt][1], h, l);
            *(unsigned*)(Ch + (size_t)r0*ldc + c0) = h;
            *(unsigned*)(Cl + (size_t)r0*ldc + c0) = l;
            split_pack(acc[mt][nt][2], acc[mt][nt][3], h, l);
            *(unsigned*)(Ch + (size_t)(r0+8)*ldc + c0) = h;
            *(unsigned*)(Cl + (size_t)(r0+8)*ldc + c0) = l;
        }
}

// ---------------- fp32 NT core (vout only) ---------------------------------
__device__ __forceinline__ void gemm_nt_core(
    const float* __restrict__ A, int lda,
    const float* __restrict__ B, int ldb,
    float* __restrict__ C, int ldc,
    int K, float scale, const float* __restrict__ bias)
{
    __shared__ float As[16*68];
    __shared__ float Bs[16*68];
    const int tid = threadIdx.x;
    const int tx = tid & 15, ty = tid >> 4;
    const int lr = tid >> 2;
    const int lk = (tid & 3) << 2;
    const int row0 = blockIdx.y * 64;
    const int col0 = blockIdx.x * 64;
    const float* Ap = A + (size_t)(row0 + lr) * lda + lk;
    const float* Bp = B + (size_t)(col0 + lr) * ldb + lk;
    float acc[4][4] = {};
    for (int kk = 0; kk < K; kk += 16) {
        float4 av = *(const float4*)(Ap + kk);
        float4 bv = *(const float4*)(Bp + kk);
        __syncthreads();
        As[(lk+0)*68+lr]=av.x; As[(lk+1)*68+lr]=av.y;
        As[(lk+2)*68+lr]=av.z; As[(lk+3)*68+lr]=av.w;
        Bs[(lk+0)*68+lr]=bv.x; Bs[(lk+1)*68+lr]=bv.y;
        Bs[(lk+2)*68+lr]=bv.z; Bs[(lk+3)*68+lr]=bv.w;
        __syncthreads();
#pragma unroll
        for (int k = 0; k < 16; k++) {
            float4 a4 = *(const float4*)&As[k*68 + ty*4];
            float4 b4 = *(const float4*)&Bs[k*68 + tx*4];
            float a_[4] = {a4.x, a4.y, a4.z, a4.w};
            float b_[4] = {b4.x, b4.y, b4.z, b4.w};
#pragma unroll
            for (int i = 0; i < 4; i++)
#pragma unroll
                for (int j = 0; j < 4; j++)
                    acc[i][j] = fmaf(a_[i], b_[j], acc[i][j]);
        }
    }
#pragma unroll
    for (int i = 0; i < 4; i++) {
        float4 o;
        o.x = acc[i][0]*scale + bias[col0+tx*4+0];
        o.y = acc[i][1]*scale + bias[col0+tx*4+1];
        o.z = acc[i][2]*scale + bias[col0+tx*4+2];
        o.w = acc[i][3]*scale + bias[col0+tx*4+3];
        *(float4*)&C[(size_t)(row0+ty*4+i)*ldc + col0 + tx*4] = o;
    }
}

// ================= kernels ==================================================

// split fp32 inputs -> bf16 hi/lo
__global__ void __launch_bounds__(256) aa_cvt(
    const float* __restrict__ q, const float* __restrict__ k,
    const float* __restrict__ val, const float* __restrict__ qp,
    const float* __restrict__ Wk)
{
    const float* src; ushort_t *dh, *dl; int n;
    switch (blockIdx.y) {
        case 0: src = q;   dh = g_qh;  dl = g_ql;  n = 1048576; break;
        case 1: src = k;   dh = g_kh;  dl = g_kl;  n = 1048576; break;
        case 2: src = val; dh = g_vh;  dl = g_vl;  n = 1048576; break;
        case 3: src = qp;  dh = g_qph; dl = g_qpl; n = 1048576; break;
        default:src = Wk;  dh = g_wkh; dl = g_wkl; n = 16384;   break;
    }
    int i = (blockIdx.x * 256 + threadIdx.x) * 4;
    if (i >= n) return;
    float4 v = *(const float4*)(src + i);
    unsigned h0,l0,h1,l1;
    split_pack(v.x, v.y, h0, l0);
    split_pack(v.z, v.w, h1, l1);
    *(uint2*)(dh + i) = make_uint2(h0, h1);
    *(uint2*)(dl + i) = make_uint2(l0, l1);
}

// stage 1 scores: g_search = scale * Q K^T
__global__ void __launch_bounds__(256) aa_t_scores1()
{
    extern __shared__ unsigned smx[];
    int bz = blockIdx.z, b = bz >> 2, x = bz & 3;
    size_t qoff = (size_t)b*524288 + x*128;
    const ushort_t* Ah = g_qh + qoff + (size_t)blockIdx.y*128*512;
    const ushort_t* Al = g_ql + qoff + (size_t)blockIdx.y*128*512;
    const ushort_t* Bh = g_kh + qoff + (size_t)blockIdx.x*64*512;
    const ushort_t* Bl = g_kl + qoff + (size_t)blockIdx.x*64*512;
    float acc[2][4][4] = {};
    mma_core<0>(smx, Ah, Al, 512, Bh, Bl, 512, 128, acc);
    float* C = g_search + (size_t)bz*1048576 + (size_t)blockIdx.y*128*1024 + blockIdx.x*64;
    epilogue_f32(acc, C, 1024, SCALE);
}

// row softmax over s; emits bf16 hi/lo Search
__global__ void __launch_bounds__(256) aa_k_softmax()
{
    size_t row = blockIdx.x;
    const float* p = g_search + row * 1024;
    int tid = threadIdx.x;
    float4 v4 = *(const float4*)(p + tid*4);
    float v[4] = {v4.x, v4.y, v4.z, v4.w};
    float m = fmaxf(fmaxf(v[0], v[1]), fmaxf(v[2], v[3]));
    __shared__ float red[256];
    red[tid] = m; __syncthreads();
    for (int s = 128; s > 0; s >>= 1) {
        if (tid < s) red[tid] = fmaxf(red[tid], red[tid+s]);
        __syncthreads();
    }
    m = red[0]; __syncthreads();
    float sum = 0.f;
#pragma unroll
    for (int i = 0; i < 4; i++) { v[i] = expf(v[i] - m); sum += v[i]; }
    red[tid] = sum; __syncthreads();
    for (int s = 128; s > 0; s >>= 1) {
        if (tid < s) red[tid] += red[tid+s];
        __syncthreads();
    }
    float inv = 1.f / red[0];
    unsigned h0,l0,h1,l1;
    split_pack(v[0]*inv, v[1]*inv, h0, l0);
    split_pack(v[2]*inv, v[3]*inv, h1, l1);
    *(uint2*)(g_sh + row*1024 + tid*4) = make_uint2(h0, h1);
    *(uint2*)(g_sl + row*1024 + tid*4) = make_uint2(l0, l1);
}

// Retrieval planes (NN): out bf16 hi/lo g_r[plane][m][e]
__global__ void __launch_bounds__(256) aa_t_retr()
{
    extern __shared__ unsigned smx[];
    int bz = blockIdx.z, b = bz >> 2, x = bz & 3;
    int n0 = blockIdx.x * 64;
    if (n0 >= (x + 1) * 128) return;
    const ushort_t* Ah = g_sh + (size_t)bz*1048576 + (size_t)blockIdx.y*128*1024;
    const ushort_t* Al = g_sl + (size_t)bz*1048576 + (size_t)blockIdx.y*128*1024;
    const ushort_t* Bh = g_vh + (size_t)b*524288 + n0;
    const ushort_t* Bl = g_vl + (size_t)b*524288 + n0;
    float acc[2][4][4] = {};
    mma_core<1>(smx, Ah, Al, 1024, Bh, Bl, 512, 1024, acc);
    int y = n0 >> 7;
    size_t coff = ((size_t)(bz*4 + y))*131072 + (size_t)blockIdx.y*128*128 + (n0 & 127);
    epilogue_bf16(acc, g_rh + coff, g_rl + coff, 128);
}

// qk = q_plus @ Wk (NN, bias cancels in softmax) -> bf16 hi/lo
__global__ void __launch_bounds__(256) aa_t_qk()
{
    extern __shared__ unsigned smx[];
    const ushort_t* Ah = g_qph + (size_t)blockIdx.y*128*128;
    const ushort_t* Al = g_qpl + (size_t)blockIdx.y*128*128;
    float acc[2][4][4] = {};
    mma_core<1>(smx, Ah, Al, 128, g_wkh + blockIdx.x*64, g_wkl + blockIdx.x*64, 128, 128, acc);
    size_t coff = (size_t)blockIdx.y*128*128 + blockIdx.x*64;
    epilogue_bf16(acc, g_qkh + coff, g_qkl + coff, 128);
}

// stage-2 scores planes (NT): g_s2[plane] = scale * qk · R^T
__global__ void __launch_bounds__(256) aa_t_scores2()
{
    extern __shared__ unsigned smx[];
    int t = blockIdx.z, b = t / 10, u = t % 10;
    int x = c_xy_x[u], y = c_xy_y[u];
    size_t aoff = (size_t)b*524288 + x*128 + (size_t)blockIdx.y*128*512;
    size_t boff = ((size_t)((b*4 + x)*4 + y))*131072 + (size_t)blockIdx.x*64*128;
    float acc[2][4][4] = {};
    mma_core<0>(smx, g_qkh + aoff, g_qkl + aoff, 512, g_rh + boff, g_rl + boff, 128, 128, acc);
    float* C = g_s2 + ((size_t)(b*10 + u))*1048576
             + (size_t)blockIdx.y*128*1024 + blockIdx.x*64;
    epilogue_f32(acc, C, 1024, SCALE);
}

// softmax over y across planes -> series bf16 hi/lo
__global__ void __launch_bounds__(256) aa_k_softmax2()
{
    int blk = blockIdx.x;
    int l = blk & 1023;
    int x = (blk >> 10) & 3;
    int b = blk >> 12;
    int ny = x + 1;
    size_t pbase = ((size_t)(b*10 + c_tri[x]))*1048576 + (size_t)l*1024 + threadIdx.x*4;
    float4 v[4];
#pragma unroll
    for (int y = 0; y < 4; y++)
        if (y < ny) v[y] = *(const float4*)(g_s2 + pbase + (size_t)y*1048576);
        else        v[y] = make_float4(-1e30f,-1e30f,-1e30f,-1e30f);
    float4 mx;
    mx.x = fmaxf(fmaxf(v[0].x,v[1].x), fmaxf(v[2].x,v[3].x));
    mx.y = fmaxf(fmaxf(v[0].y,v[1].y), fmaxf(v[2].y,v[3].y));
    mx.z = fmaxf(fmaxf(v[0].z,v[1].z), fmaxf(v[2].z,v[3].z));
    mx.w = fmaxf(fmaxf(v[0].w,v[1].w), fmaxf(v[2].w,v[3].w));
    float4 s = make_float4(0,0,0,0);
#pragma unroll
    for (int y = 0; y < 4; y++) {
        if (y < ny) {
            v[y].x = expf(v[y].x - mx.x); s.x += v[y].x;
            v[y].y = expf(v[y].y - mx.y); s.y += v[y].y;
            v[y].z = expf(v[y].z - mx.z); s.z += v[y].z;
            v[y].w = expf(v[y].w - mx.w); s.w += v[y].w;
        }
    }
    float4 inv = make_float4(1.f/s.x, 1.f/s.y, 1.f/s.z, 1.f/s.w);
#pragma unroll
    for (int y = 0; y < 4; y++) {
        if (y < ny) {
            unsigned h0,l0,h1,l1;
            split_pack(v[y].x*inv.x, v[y].y*inv.y, h0, l0);
            split_pack(v[y].z*inv.z, v[y].w*inv.w, h1, l1);
            *(uint2*)(g_s2h + pbase + (size_t)y*1048576) = make_uint2(h0, h1);
            *(uint2*)(g_s2l + pbase + (size_t)y*1048576) = make_uint2(l0, l1);
        }
    }
}

// catt (NN, accumulate over y): V[b,l,e,x]
__global__ void __launch_bounds__(256) aa_t_catt()
{
    extern __shared__ unsigned smx[];
    int bz = blockIdx.z, b = bz >> 2, x = bz & 3, ny = x + 1;
    float acc[2][4][4] = {};
    for (int y = 0; y < ny; y++) {
        size_t aoff = ((size_t)(b*10 + c_tri[x] + y))*1048576 + (size_t)blockIdx.y*128*1024;
        size_t boff = ((size_t)(bz*4 + y))*131072 + blockIdx.x*64;
        mma_core<1>(smx, g_s2h + aoff, g_s2l + aoff, 1024, g_rh + boff, g_rl + boff, 128, 1024, acc);
    }
    const int lane = threadIdx.x & 31, w = threadIdx.x >> 5;
    const int g = lane >> 2, tg = lane & 3;
    const int wrow = w >> 1, wcol = w & 1;
    const int l0 = blockIdx.y*128, e0 = blockIdx.x*64;
#pragma unroll
    for (int mt = 0; mt < 2; mt++)
#pragma unroll
        for (int nt = 0; nt < 4; nt++) {
            int r = l0 + wrow*32 + mt*16 + g;
            int c = e0 + wcol*32 + nt*8 + 2*tg;
            g_vpart[(((size_t)b*1024 + r  )*128 + c  )*4 + x] = acc[mt][nt][0];
            g_vpart[(((size_t)b*1024 + r  )*128 + c+1)*4 + x] = acc[mt][nt][1];
            g_vpart[(((size_t)b*1024 + r+8)*128 + c  )*4 + x] = acc[mt][nt][2];
            g_vpart[(((size_t)b*1024 + r+8)*128 + c+1)*4 + x] = acc[mt][nt][3];
        }
}

// V output: g_vpart (viewed [8192,128]) @ Wv^T + bv — fp32, tiny
__global__ void __launch_bounds__(256) aa_k_vout(const float* __restrict__ Wv,
                                                 const float* __restrict__ bv,
                                                 float* __restrict__ out)
{
    gemm_nt_core(g_vpart, EE, Wv, EE, out, EE, EE, 1.0f, bv);
}

// series_out == 0.25 everywhere (float4)
__global__ void __launch_bounds__(256) aa_k_fill(float4* __restrict__ p, float v)
{
    p[(size_t)blockIdx.x * 256 + threadIdx.x] = make_float4(v, v, v, v);
}

// prior + sig (bit-exact libdevice path — DO NOT CHANGE)
__global__ void __launch_bounds__(256) aa_k_prior(const float* __restrict__ sigma,
                                                  float* __restrict__ prior,
                                                  float* __restrict__ sig_out)
{
    int row = blockIdx.x;
    int i = row & 1023;
    int h = (row >> 10) & 3;
    int b = row >> 12;
    float v = sigma[((size_t)b*LL + i)*XX + h];
    float s = sig_transform(v);
    if (threadIdx.x == 0) sig_out[row] = s;
    float denom = 2.5066282746310002f * s;
    float coef = 1.0f / denom;
    float s2 = s * s;
    float* p = prior + (size_t)row * LL;
    float fi = (float)i;
    for (int j = threadIdx.x; j < LL; j += 256) {
        float d = fabsf(fi - (float)j);
        float d2 = d * d;
        float num = -d2 * 0.5f;
        float arg = num / s2;
        p[j] = coef * expf(arg);
    }
}

// =========================================================================
extern "C" void kernel_launch(void* const* d_in, const int* in_sizes, int n_in,
                              void* d_out, int out_size)
{
    const float* big[5] = {};
    int nbig = 0;
    const float* sigma = nullptr;
    const float* w[2] = {};
    int nw = 0;
    const float* bias[2] = {};
    int nb = 0;
    for (int i = 0; i < n_in; i++) {
        int sz = in_sizes[i];
        if (sz == BB*LL*XX*EE)      { if (nbig < 5) big[nbig++] = (const float*)d_in[i]; }
        else if (sz == BB*LL*XX)    { sigma = (const float*)d_in[i]; }
        else if (sz == EE*EE)       { if (nw < 2) w[nw++] = (const float*)d_in[i]; }
        else if (sz == EE)          { if (nb < 2) bias[nb++] = (const float*)d_in[i]; }
    }
    const float* query = big[1];
    const float* key_  = big[2];
    const float* value = big[3];
    const float* qplus = big[4];
    const float* Wk = w[0];
    const float* Wv = w[1];    const float* bv = bias[1];

    float* out       = (float*)d_out;
    float* outV      = out;
    float* outSeries = out + 1048576;
    float* outPrior  = out + 1048576 + 8388608;
    float* outSig    = out + 1048576 + 2*8388608;

    static int smem_set = 0;
    if (!smem_set) {
        cudaFuncSetAttribute(aa_t_scores1, cudaFuncAttributeMaxDynamicSharedMemorySize, SMEM_MMA);
        cudaFuncSetAttribute(aa_t_retr,    cudaFuncAttributeMaxDynamicSharedMemorySize, SMEM_MMA);
        cudaFuncSetAttribute(aa_t_qk,      cudaFuncAttributeMaxDynamicSharedMemorySize, SMEM_MMA);
        cudaFuncSetAttribute(aa_t_scores2, cudaFuncAttributeMaxDynamicSharedMemorySize, SMEM_MMA);
        cudaFuncSetAttribute(aa_t_catt,    cudaFuncAttributeMaxDynamicSharedMemorySize, SMEM_MMA);
        smem_set = 1;
    }

    dim3 thr(256);
    aa_cvt      <<<dim3(1024,5),   thr>>>(query, key_, value, qplus, Wk);
    aa_t_scores1<<<dim3(16,8,8),   thr, SMEM_MMA>>>();
    aa_k_softmax<<<dim3(8192),     thr>>>();
    aa_t_retr   <<<dim3(8,8,8),    thr, SMEM_MMA>>>();
    aa_t_qk     <<<dim3(2,64),     thr, SMEM_MMA>>>();
    aa_t_scores2<<<dim3(16,8,20),  thr, SMEM_MMA>>>();
    aa_k_softmax2<<<dim3(8192),    thr>>>();
    aa_t_catt   <<<dim3(2,8,8),    thr, SMEM_MMA>>>();
    aa_k_vout   <<<dim3(2,128),    thr>>>(Wv, bv, outV);
    aa_k_fill   <<<dim3(8192),     thr>>>((float4*)outSeries, 0.25f);
    aa_k_prior  <<<dim3(8192),     thr>>>(sigma, outPrior, outSig);
}

// round 13
// speedup vs baseline: 1.0359x; 1.0359x over previous
#include <cuda_runtime.h>
#include <math.h>

#define BB 2
#define LL 1024
#define XX 4
#define EE 128
#define YY 4
#define SCALE 0.08838834764831845f   // 1/sqrt(128)

typedef unsigned short ushort_t;

// ---------------- scratch (static device globals) --------------------------
__device__ float g_search[8*1024*1024];                 // stage1 scores fp32  32 MB
__device__ float g_s2    [2*10*1024*1024];              // stage2 scores fp32  80 MB
__device__ float g_vpart [BB*LL*EE*XX];                 // [b][l][e][x]         4 MB

__device__ __align__(16) ushort_t g_qh [2*1024*4*128], g_ql [2*1024*4*128];
__device__ __align__(16) ushort_t g_kh [2*1024*4*128], g_kl [2*1024*4*128];
__device__ __align__(16) ushort_t g_vh [2*1024*512],   g_vl [2*1024*512];
__device__ __align__(16) ushort_t g_qph[2*1024*4*128], g_qpl[2*1024*4*128];
__device__ __align__(16) ushort_t g_wkh[128*128],      g_wkl[128*128];
__device__ __align__(16) ushort_t g_sh [8*1024*1024],  g_sl [8*1024*1024];   // Search bf16
__device__ __align__(16) ushort_t g_qkh[2*1024*4*128], g_qkl[2*1024*4*128];
__device__ __align__(16) ushort_t g_rh [2*4*4*1024*128], g_rl[2*4*4*1024*128];
__device__ __align__(16) ushort_t g_s2h[2*10*1024*1024], g_s2l[2*10*1024*1024];

__constant__ int c_xy_x[10] = {0,1,1,2,2,2,3,3,3,3};
__constant__ int c_xy_y[10] = {0,0,1,0,1,2,0,1,2,3};
__constant__ int c_tri[4]  = {0,1,3,6};

// libdevice path — bit-matches jax-on-GPU reference. DO NOT CHANGE.
__device__ __forceinline__ float sig_transform(float v) {
    float t = 5.0f * v;
    float e = expf(-t);
    float sigmoid = 1.0f / (1.0f + e);
    float sg = sigmoid + 1e-5f;
    float p = powf(3.0f, sg);
    return p - 1.0f;
}

// ================= bf16 split helpers =======================================
__device__ __forceinline__ unsigned bfbits(float x) {
    unsigned u = __float_as_uint(x);
    return (u + 0x7fffu + ((u >> 16) & 1u)) >> 16;
}
__device__ __forceinline__ float bfval(unsigned b) { return __uint_as_float(b << 16); }
__device__ __forceinline__ void split_pack(float x0, float x1, unsigned &hi, unsigned &lo) {
    unsigned h0 = bfbits(x0), h1 = bfbits(x1);
    unsigned l0 = bfbits(x0 - bfval(h0)), l1 = bfbits(x1 - bfval(h1));
    hi = h0 | (h1 << 16);
    lo = l0 | (l1 << 16);
}
__device__ __forceinline__ void mma_bf16(float (&c)[4],
    unsigned a0, unsigned a1, unsigned a2, unsigned a3,
    unsigned b0, unsigned b1)
{
    asm volatile("mma.sync.aligned.m16n8k16.row.col.f32.bf16.bf16.f32 "
        "{%0,%1,%2,%3},{%4,%5,%6,%7},{%8,%9},{%0,%1,%2,%3};"
        : "+f"(c[0]), "+f"(c[1]), "+f"(c[2]), "+f"(c[3])
        : "r"(a0), "r"(a1), "r"(a2), "r"(a3), "r"(b0), "r"(b1));
}
__device__ __forceinline__ void ldsm_x4(unsigned &r0, unsigned &r1,
                                        unsigned &r2, unsigned &r3, unsigned addr)
{
    asm volatile("ldmatrix.sync.aligned.m8n8.x4.shared.b16 {%0,%1,%2,%3}, [%4];"
        : "=r"(r0), "=r"(r1), "=r"(r2), "=r"(r3) : "r"(addr));
}
__device__ __forceinline__ void ldsm_x4t(unsigned &r0, unsigned &r1,
                                         unsigned &r2, unsigned &r3, unsigned addr)
{
    asm volatile("ldmatrix.sync.aligned.m8n8.x4.trans.shared.b16 {%0,%1,%2,%3}, [%4];"
        : "=r"(r0), "=r"(r1), "=r"(r2), "=r"(r3) : "r"(addr));
}
__device__ __forceinline__ void cp_async16(void* dst, const void* src) {
    unsigned s = (unsigned)__cvta_generic_to_shared(dst);
    asm volatile("cp.async.cg.shared.global [%0], [%1], 16;" :: "r"(s), "l"(src));
}
#define CP_COMMIT() asm volatile("cp.async.commit_group;")
template<int N>
__device__ __forceinline__ void cp_wait() {
    asm volatile("cp.async.wait_group %0;" :: "n"(N));
}

// C tile 128x64, 256 threads (8 warps = 4x2 grid of 32x32 warp tiles).
// Operands pre-split bf16 hi/lo in gmem; lda/ldb in bf16 elements.
// TRANSB=0: B is [n][k] (NT). TRANSB=1: B is [k][n] (NN, via ldmatrix.trans).
// 2-stage cp.async double buffer (dynamic smem, 2 * 30 KB).
// Stage s layout (words): SA_hi [0,2560) SA_lo [2560,5120) SB_hi/lo [5120,7680)
template<int TRANSB>
__device__ __forceinline__ void mma_core(
    unsigned* __restrict__ SM_,
    const ushort_t* __restrict__ Ahg, const ushort_t* __restrict__ Alg, int lda,
    const ushort_t* __restrict__ Bhg, const ushort_t* __restrict__ Blg, int ldb,
    int K, float (&acc)[2][4][4])
{
    const int tid = threadIdx.x;
    const int lane = tid & 31, w = tid >> 5;
    const int wrow = w >> 1, wcol = w & 1;
    const int lm = lane & 15, lq = lane >> 4;

    const int ar = tid >> 1, ax = tid & 1;    // A staging: 2 thr/row, 16 ushort each
    const int br = tid >> 2, bq = tid & 3;    // B NT: 4 thr/row, 8 ushort each
    const int half = tid >> 7, t7 = tid & 127;
    const int nr = t7 >> 2, nq = t7 & 3;      // B NN: per plane-half, 16 ushort each

    auto prefetch = [&](int kk, int s) {
        unsigned* SA = SM_ + s * 7680;
        unsigned* SB = SA + 5120;
        const ushort_t* pa = Ahg + (size_t)ar*lda + kk + ax*16;
        const ushort_t* pl = Alg + (size_t)ar*lda + kk + ax*16;
        cp_async16(&SA[ar*20 + ax*8],            pa);
        cp_async16(&SA[ar*20 + ax*8 + 4],        pa + 8);
        cp_async16(&SA[2560 + ar*20 + ax*8],     pl);
        cp_async16(&SA[2560 + ar*20 + ax*8 + 4], pl + 8);
        if (TRANSB) {
            const ushort_t* pb = (half ? Blg : Bhg) + (size_t)(kk + nr)*ldb + nq*16;
            ushort_t* bd = (ushort_t*)(SB + half*1280) + nr*72 + nq*16;
            cp_async16(bd,     pb);
            cp_async16(bd + 8, pb + 8);
        } else {
            cp_async16(&SB[br*20 + bq*4],        Bhg + (size_t)br*ldb + kk + bq*8);
            cp_async16(&SB[1280 + br*20 + bq*4], Blg + (size_t)br*ldb + kk + bq*8);
        }
    };

    const int nck = K >> 5;
    prefetch(0, 0); CP_COMMIT();
    for (int c = 0; c < nck; c++) {
        if (c + 1 < nck) { prefetch((c+1) << 5, (c+1) & 1); CP_COMMIT(); cp_wait<1>(); }
        else             { cp_wait<0>(); }
        __syncthreads();
        unsigned* SA = SM_ + (c & 1) * 7680;
        unsigned* SB = SA + 5120;
#pragma unroll
        for (int k16 = 0; k16 < 2; k16++) {
            const int ko = k16*8;
            unsigned ah[2][4], al[2][4], bh[4][2], bl[4][2];
#pragma unroll
            for (int mt = 0; mt < 2; mt++) {
                int m = wrow*32 + mt*16;
                unsigned aw = (unsigned)__cvta_generic_to_shared(
                    &SA[(m + lm)*20 + ko + (lq<<2)]);
                ldsm_x4(ah[mt][0], ah[mt][1], ah[mt][2], ah[mt][3], aw);
                ldsm_x4(al[mt][0], al[mt][1], al[mt][2], al[mt][3], aw + 2560*4);
            }
#pragma unroll
            for (int p = 0; p < 2; p++) {
                int n0 = wcol*32 + p*16;
                if (TRANSB) {
                    const ushort_t* bb = (const ushort_t*)SB;
                    unsigned bw = (unsigned)__cvta_generic_to_shared(
                        bb + (k16*16 + lm)*72 + n0 + (lq<<3));
                    ldsm_x4t(bh[2*p][0], bh[2*p][1], bh[2*p+1][0], bh[2*p+1][1], bw);
                    ldsm_x4t(bl[2*p][0], bl[2*p][1], bl[2*p+1][0], bl[2*p+1][1], bw + 1280*4);
                } else {
                    unsigned bw = (unsigned)__cvta_generic_to_shared(
                        &SB[(n0 + lm)*20 + ko + (lq<<2)]);
                    ldsm_x4(bh[2*p][0], bh[2*p+1][0], bh[2*p][1], bh[2*p+1][1], bw);
                    ldsm_x4(bl[2*p][0], bl[2*p+1][0], bl[2*p][1], bl[2*p+1][1], bw + 1280*4);
                }
            }
#pragma unroll
            for (int mt = 0; mt < 2; mt++)
#pragma unroll
                for (int nt = 0; nt < 4; nt++) {
                    mma_bf16(acc[mt][nt], ah[mt][0],ah[mt][1],ah[mt][2],ah[mt][3], bh[nt][0],bh[nt][1]);
                    mma_bf16(acc[mt][nt], ah[mt][0],ah[mt][1],ah[mt][2],ah[mt][3], bl[nt][0],bl[nt][1]);
                    mma_bf16(acc[mt][nt], al[mt][0],al[mt][1],al[mt][2],al[mt][3], bh[nt][0],bh[nt][1]);
                }
        }
        __syncthreads();
    }
}

#define SMEM_MMA (2*7680*4)   // 61440 bytes -> 3 blocks/SM

__device__ __forceinline__ void epilogue_f32(
    float (&acc)[2][4][4], float* C, int ldc, float scale)
{
    const int lane = threadIdx.x & 31, w = threadIdx.x >> 5;
    const int g = lane >> 2, tg = lane & 3;
    const int wrow = w >> 1, wcol = w & 1;
#pragma unroll
    for (int mt = 0; mt < 2; mt++)
#pragma unroll
        for (int nt = 0; nt < 4; nt++) {
            int r0 = wrow*32 + mt*16 + g;
            int c0 = wcol*32 + nt*8 + 2*tg;
            float2 v0 = {acc[mt][nt][0]*scale, acc[mt][nt][1]*scale};
            float2 v1 = {acc[mt][nt][2]*scale, acc[mt][nt][3]*scale};
            *(float2*)(C + (size_t)r0*ldc + c0) = v0;
            *(float2*)(C + (size_t)(r0+8)*ldc + c0) = v1;
        }
}

__device__ __forceinline__ void epilogue_bf16(
    float (&acc)[2][4][4], ushort_t* Ch, ushort_t* Cl, int ldc)
{
    const int lane = threadIdx.x & 31, w = threadIdx.x >> 5;
    const int g = lane >> 2, tg = lane & 3;
    const int wrow = w >> 1, wcol = w & 1;
#pragma unroll
    for (int mt = 0; mt < 2; mt++)
#pragma unroll
        for (int nt = 0; nt < 4; nt++) {
            int r0 = wrow*32 + mt*16 + g;
            int c0 = wcol*32 + nt*8 + 2*tg;
            unsigned h, l;
            split_pack(acc[mt][nt][0], acc[mt][nt][1], h, l);
            *(unsigned*)(Ch + (size_t)r0*ldc + c0) = h;
            *(unsigned*)(Cl + (size_t)r0*ldc + c0) = l;
            split_pack(acc[mt][nt][2], acc[mt][nt][3], h, l);
            *(unsigned*)(Ch + (size_t)(r0+8)*ldc + c0) = h;
            *(unsigned*)(Cl + (size_t)(r0+8)*ldc + c0) = l;
        }
}

// ---------------- fp32 NT core (vout only) ---------------------------------
__device__ __forceinline__ void gemm_nt_core(
    const float* __restrict__ A, int lda,
    const float* __restrict__ B, int ldb,
    float* __restrict__ C, int ldc,
    int K, float scale, const float* __restrict__ bias)
{
    __shared__ float As[16*68];
    __shared__ float Bs[16*68];
    const int tid = threadIdx.x;
    const int tx = tid & 15, ty = tid >> 4;
    const int lr = tid >> 2;
    const int lk = (tid & 3) << 2;
    const int row0 = blockIdx.y * 64;
    const int col0 = blockIdx.x * 64;
    const float* Ap = A + (size_t)(row0 + lr) * lda + lk;
    const float* Bp = B + (size_t)(col0 + lr) * ldb + lk;
    float acc[4][4] = {};
    for (int kk = 0; kk < K; kk += 16) {
        float4 av = *(const float4*)(Ap + kk);
        float4 bv = *(const float4*)(Bp + kk);
        __syncthreads();
        As[(lk+0)*68+lr]=av.x; As[(lk+1)*68+lr]=av.y;
        As[(lk+2)*68+lr]=av.z; As[(lk+3)*68+lr]=av.w;
        Bs[(lk+0)*68+lr]=bv.x; Bs[(lk+1)*68+lr]=bv.y;
        Bs[(lk+2)*68+lr]=bv.z; Bs[(lk+3)*68+lr]=bv.w;
        __syncthreads();
#pragma unroll
        for (int k = 0; k < 16; k++) {
            float4 a4 = *(const float4*)&As[k*68 + ty*4];
            float4 b4 = *(const float4*)&Bs[k*68 + tx*4];
            float a_[4] = {a4.x, a4.y, a4.z, a4.w};
            float b_[4] = {b4.x, b4.y, b4.z, b4.w};
#pragma unroll
            for (int i = 0; i < 4; i++)
#pragma unroll
                for (int j = 0; j < 4; j++)
                    acc[i][j] = fmaf(a_[i], b_[j], acc[i][j]);
        }
    }
#pragma unroll
    for (int i = 0; i < 4; i++) {
        float4 o;
        o.x = acc[i][0]*scale + bias[col0+tx*4+0];
        o.y = acc[i][1]*scale + bias[col0+tx*4+1];
        o.z = acc[i][2]*scale + bias[col0+tx*4+2];
        o.w = acc[i][3]*scale + bias[col0+tx*4+3];
        *(float4*)&C[(size_t)(row0+ty*4+i)*ldc + col0 + tx*4] = o;
    }
}

// ================= kernels ==================================================

// split fp32 inputs -> bf16 hi/lo
__global__ void __launch_bounds__(256) aa_cvt(
    const float* __restrict__ q, const float* __restrict__ k,
    const float* __restrict__ val, const float* __restrict__ qp,
    const float* __restrict__ Wk)
{
    const float* src; ushort_t *dh, *dl; int n;
    switch (blockIdx.y) {
        case 0: src = q;   dh = g_qh;  dl = g_ql;  n = 1048576; break;
        case 1: src = k;   dh = g_kh;  dl = g_kl;  n = 1048576; break;
        case 2: src = val; dh = g_vh;  dl = g_vl;  n = 1048576; break;
        case 3: src = qp;  dh = g_qph; dl = g_qpl; n = 1048576; break;
        default:src = Wk;  dh = g_wkh; dl = g_wkl; n = 16384;   break;
    }
    int i = (blockIdx.x * 256 + threadIdx.x) * 4;
    if (i >= n) return;
    float4 v = *(const float4*)(src + i);
    unsigned h0,l0,h1,l1;
    split_pack(v.x, v.y, h0, l0);
    split_pack(v.z, v.w, h1, l1);
    *(uint2*)(dh + i) = make_uint2(h0, h1);
    *(uint2*)(dl + i) = make_uint2(l0, l1);
}

// stage 1 scores: g_search = scale * Q K^T
__global__ void __launch_bounds__(256, 3) aa_t_scores1()
{
    extern __shared__ unsigned smx[];
    int bz = blockIdx.z, b = bz >> 2, x = bz & 3;
    size_t qoff = (size_t)b*524288 + x*128;
    const ushort_t* Ah = g_qh + qoff + (size_t)blockIdx.y*128*512;
    const ushort_t* Al = g_ql + qoff + (size_t)blockIdx.y*128*512;
    const ushort_t* Bh = g_kh + qoff + (size_t)blockIdx.x*64*512;
    const ushort_t* Bl = g_kl + qoff + (size_t)blockIdx.x*64*512;
    float acc[2][4][4] = {};
    mma_core<0>(smx, Ah, Al, 512, Bh, Bl, 512, 128, acc);
    float* C = g_search + (size_t)bz*1048576 + (size_t)blockIdx.y*128*1024 + blockIdx.x*64;
    epilogue_f32(acc, C, 1024, SCALE);
}

// row softmax over s; emits bf16 hi/lo Search
__global__ void __launch_bounds__(256) aa_k_softmax()
{
    size_t row = blockIdx.x;
    const float* p = g_search + row * 1024;
    int tid = threadIdx.x;
    float4 v4 = *(const float4*)(p + tid*4);
    float v[4] = {v4.x, v4.y, v4.z, v4.w};
    float m = fmaxf(fmaxf(v[0], v[1]), fmaxf(v[2], v[3]));
    __shared__ float red[256];
    red[tid] = m; __syncthreads();
    for (int s = 128; s > 0; s >>= 1) {
        if (tid < s) red[tid] = fmaxf(red[tid], red[tid+s]);
        __syncthreads();
    }
    m = red[0]; __syncthreads();
    float sum = 0.f;
#pragma unroll
    for (int i = 0; i < 4; i++) { v[i] = expf(v[i] - m); sum += v[i]; }
    red[tid] = sum; __syncthreads();
    for (int s = 128; s > 0; s >>= 1) {
        if (tid < s) red[tid] += red[tid+s];
        __syncthreads();
    }
    float inv = 1.f / red[0];
    unsigned h0,l0,h1,l1;
    split_pack(v[0]*inv, v[1]*inv, h0, l0);
    split_pack(v[2]*inv, v[3]*inv, h1, l1);
    *(uint2*)(g_sh + row*1024 + tid*4) = make_uint2(h0, h1);
    *(uint2*)(g_sl + row*1024 + tid*4) = make_uint2(l0, l1);
}

// Retrieval planes (NN): out bf16 hi/lo g_r[plane][m][e]
__global__ void __launch_bounds__(256, 3) aa_t_retr()
{
    extern __shared__ unsigned smx[];
    int bz = blockIdx.z, b = bz >> 2, x = bz & 3;
    int n0 = blockIdx.x * 64;
    if (n0 >= (x + 1) * 128) return;
    const ushort_t* Ah = g_sh + (size_t)bz*1048576 + (size_t)blockIdx.y*128*1024;
    const ushort_t* Al = g_sl + (size_t)bz*1048576 + (size_t)blockIdx.y*128*1024;
    const ushort_t* Bh = g_vh + (size_t)b*524288 + n0;
    const ushort_t* Bl = g_vl + (size_t)b*524288 + n0;
    float acc[2][4][4] = {};
    mma_core<1>(smx, Ah, Al, 1024, Bh, Bl, 512, 1024, acc);
    int y = n0 >> 7;
    size_t coff = ((size_t)(bz*4 + y))*131072 + (size_t)blockIdx.y*128*128 + (n0 & 127);
    epilogue_bf16(acc, g_rh + coff, g_rl + coff, 128);
}

// qk = q_plus @ Wk (NN, bias cancels in softmax) -> bf16 hi/lo
__global__ void __launch_bounds__(256, 3) aa_t_qk()
{
    extern __shared__ unsigned smx[];
    const ushort_t* Ah = g_qph + (size_t)blockIdx.y*128*128;
    const ushort_t* Al = g_qpl + (size_t)blockIdx.y*128*128;
    float acc[2][4][4] = {};
    mma_core<1>(smx, Ah, Al, 128, g_wkh + blockIdx.x*64, g_wkl + blockIdx.x*64, 128, 128, acc);
    size_t coff = (size_t)blockIdx.y*128*128 + blockIdx.x*64;
    epilogue_bf16(acc, g_qkh + coff, g_qkl + coff, 128);
}

// stage-2 scores planes (NT): g_s2[plane] = scale * qk · R^T
__global__ void __launch_bounds__(256, 3) aa_t_scores2()
{
    extern __shared__ unsigned smx[];
    int t = blockIdx.z, b = t / 10, u = t % 10;
    int x = c_xy_x[u], y = c_xy_y[u];
    size_t aoff = (size_t)b*524288 + x*128 + (size_t)blockIdx.y*128*512;
    size_t boff = ((size_t)((b*4 + x)*4 + y))*131072 + (size_t)blockIdx.x*64*128;
    float acc[2][4][4] = {};
    mma_core<0>(smx, g_qkh + aoff, g_qkl + aoff, 512, g_rh + boff, g_rl + boff, 128, 128, acc);
    float* C = g_s2 + ((size_t)(b*10 + u))*1048576
             + (size_t)blockIdx.y*128*1024 + blockIdx.x*64;
    epilogue_f32(acc, C, 1024, SCALE);
}

// softmax over y across planes -> series bf16 hi/lo
__global__ void __launch_bounds__(256) aa_k_softmax2()
{
    int blk = blockIdx.x;
    int l = blk & 1023;
    int x = (blk >> 10) & 3;
    int b = blk >> 12;
    int ny = x + 1;
    size_t pbase = ((size_t)(b*10 + c_tri[x]))*1048576 + (size_t)l*1024 + threadIdx.x*4;
    float4 v[4];
#pragma unroll
    for (int y = 0; y < 4; y++)
        if (y < ny) v[y] = *(const float4*)(g_s2 + pbase + (size_t)y*1048576);
        else        v[y] = make_float4(-1e30f,-1e30f,-1e30f,-1e30f);
    float4 mx;
    mx.x = fmaxf(fmaxf(v[0].x,v[1].x), fmaxf(v[2].x,v[3].x));
    mx.y = fmaxf(fmaxf(v[0].y,v[1].y), fmaxf(v[2].y,v[3].y));
    mx.z = fmaxf(fmaxf(v[0].z,v[1].z), fmaxf(v[2].z,v[3].z));
    mx.w = fmaxf(fmaxf(v[0].w,v[1].w), fmaxf(v[2].w,v[3].w));
    float4 s = make_float4(0,0,0,0);
#pragma unroll
    for (int y = 0; y < 4; y++) {
        if (y < ny) {
            v[y].x = expf(v[y].x - mx.x); s.x += v[y].x;
            v[y].y = expf(v[y].y - mx.y); s.y += v[y].y;
            v[y].z = expf(v[y].z - mx.z); s.z += v[y].z;
            v[y].w = expf(v[y].w - mx.w); s.w += v[y].w;
        }
    }
    float4 inv = make_float4(1.f/s.x, 1.f/s.y, 1.f/s.z, 1.f/s.w);
#pragma unroll
    for (int y = 0; y < 4; y++) {
        if (y < ny) {
            unsigned h0,l0,h1,l1;
            split_pack(v[y].x*inv.x, v[y].y*inv.y, h0, l0);
            split_pack(v[y].z*inv.z, v[y].w*inv.w, h1, l1);
            *(uint2*)(g_s2h + pbase + (size_t)y*1048576) = make_uint2(h0, h1);
            *(uint2*)(g_s2l + pbase + (size_t)y*1048576) = make_uint2(l0, l1);
        }
    }
}

// catt (NN, accumulate over y): V[b,l,e,x]
__global__ void __launch_bounds__(256, 3) aa_t_catt()
{
    extern __shared__ unsigned smx[];
    int bz = blockIdx.z, b = bz >> 2, x = bz & 3, ny = x + 1;
    float acc[2][4][4] = {};
    for (int y = 0; y < ny; y++) {
        size_t aoff = ((size_t)(b*10 + c_tri[x] + y))*1048576 + (size_t)blockIdx.y*128*1024;
        size_t boff = ((size_t)(bz*4 + y))*131072 + blockIdx.x*64;
        mma_core<1>(smx, g_s2h + aoff, g_s2l + aoff, 1024, g_rh + boff, g_rl + boff, 128, 1024, acc);
    }
    const int lane = threadIdx.x & 31, w = threadIdx.x >> 5;
    const int g = lane >> 2, tg = lane & 3;
    const int wrow = w >> 1, wcol = w & 1;
    const int l0 = blockIdx.y*128, e0 = blockIdx.x*64;
#pragma unroll
    for (int mt = 0; mt < 2; mt++)
#pragma unroll
        for (int nt = 0; nt < 4; nt++) {
            int r = l0 + wrow*32 + mt*16 + g;
            int c = e0 + wcol*32 + nt*8 + 2*tg;
            g_vpart[(((size_t)b*1024 + r  )*128 + c  )*4 + x] = acc[mt][nt][0];
            g_vpart[(((size_t)b*1024 + r  )*128 + c+1)*4 + x] = acc[mt][nt][1];
            g_vpart[(((size_t)b*1024 + r+8)*128 + c  )*4 + x] = acc[mt][nt][2];
            g_vpart[(((size_t)b*1024 + r+8)*128 + c+1)*4 + x] = acc[mt][nt][3];
        }
}

// V output: g_vpart (viewed [8192,128]) @ Wv^T + bv — fp32, tiny
__global__ void __launch_bounds__(256) aa_k_vout(const float* __restrict__ Wv,
                                                 const float* __restrict__ bv,
                                                 float* __restrict__ out)
{
    gemm_nt_core(g_vpart, EE, Wv, EE, out, EE, EE, 1.0f, bv);
}

// series_out == 0.25 everywhere (float4)
__global__ void __launch_bounds__(256) aa_k_fill(float4* __restrict__ p, float v)
{
    p[(size_t)blockIdx.x * 256 + threadIdx.x] = make_float4(v, v, v, v);
}

// prior + sig (bit-exact libdevice path — DO NOT CHANGE)
__global__ void __launch_bounds__(256) aa_k_prior(const float* __restrict__ sigma,
                                                  float* __restrict__ prior,
                                                  float* __restrict__ sig_out)
{
    int row = blockIdx.x;
    int i = row & 1023;
    int h = (row >> 10) & 3;
    int b = row >> 12;
    float v = sigma[((size_t)b*LL + i)*XX + h];
    float s = sig_transform(v);
    if (threadIdx.x == 0) sig_out[row] = s;
    float denom = 2.5066282746310002f * s;
    float coef = 1.0f / denom;
    float s2 = s * s;
    float* p = prior + (size_t)row * LL;
    float fi = (float)i;
    for (int j = threadIdx.x; j < LL; j += 256) {
        float d = fabsf(fi - (float)j);
        float d2 = d * d;
        float num = -d2 * 0.5f;
        float arg = num / s2;
        p[j] = coef * expf(arg);
    }
}

// =========================================================================
extern "C" void kernel_launch(void* const* d_in, const int* in_sizes, int n_in,
                              void* d_out, int out_size)
{
    const float* big[5] = {};
    int nbig = 0;
    const float* sigma = nullptr;
    const float* w[2] = {};
    int nw = 0;
    const float* bias[2] = {};
    int nb = 0;
    for (int i = 0; i < n_in; i++) {
        int sz = in_sizes[i];
        if (sz == BB*LL*XX*EE)      { if (nbig < 5) big[nbig++] = (const float*)d_in[i]; }
        else if (sz == BB*LL*XX)    { sigma = (const float*)d_in[i]; }
        else if (sz == EE*EE)       { if (nw < 2) w[nw++] = (const float*)d_in[i]; }
        else if (sz == EE)          { if (nb < 2) bias[nb++] = (const float*)d_in[i]; }
    }
    const float* query = big[1];
    const float* key_  = big[2];
    const float* value = big[3];
    const float* qplus = big[4];
    const float* Wk = w[0];
    const float* Wv = w[1];    const float* bv = bias[1];

    float* out       = (float*)d_out;
    float* outV      = out;
    float* outSeries = out + 1048576;
    float* outPrior  = out + 1048576 + 8388608;
    float* outSig    = out + 1048576 + 2*8388608;

    static int smem_set = 0;
    if (!smem_set) {
        cudaFuncSetAttribute(aa_t_scores1, cudaFuncAttributeMaxDynamicSharedMemorySize, SMEM_MMA);
        cudaFuncSetAttribute(aa_t_retr,    cudaFuncAttributeMaxDynamicSharedMemorySize, SMEM_MMA);
        cudaFuncSetAttribute(aa_t_qk,      cudaFuncAttributeMaxDynamicSharedMemorySize, SMEM_MMA);
        cudaFuncSetAttribute(aa_t_scores2, cudaFuncAttributeMaxDynamicSharedMemorySize, SMEM_MMA);
        cudaFuncSetAttribute(aa_t_catt,    cudaFuncAttributeMaxDynamicSharedMemorySize, SMEM_MMA);
        smem_set = 1;
    }

    dim3 thr(256);
    aa_cvt      <<<dim3(1024,5),   thr>>>(query, key_, value, qplus, Wk);
    aa_t_scores1<<<dim3(16,8,8),   thr, SMEM_MMA>>>();
    aa_k_softmax<<<dim3(8192),     thr>>>();
    aa_t_retr   <<<dim3(8,8,8),    thr, SMEM_MMA>>>();
    aa_t_qk     <<<dim3(2,64),     thr, SMEM_MMA>>>();
    aa_t_scores2<<<dim3(16,8,20),  thr, SMEM_MMA>>>();
    aa_k_softmax2<<<dim3(8192),    thr>>>();
    aa_t_catt   <<<dim3(2,8,8),    thr, SMEM_MMA>>>();
    aa_k_vout   <<<dim3(2,128),    thr>>>(Wv, bv, outV);
    aa_k_fill   <<<dim3(8192),     thr>>>((float4*)outSeries, 0.25f);
    aa_k_prior  <<<dim3(8192),     thr>>>(sigma, outPrior, outSig);
}

// round 15
// speedup vs baseline: 1.1717x; 1.1311x over previous
#include <cuda_runtime.h>
#include <math.h>

#define BB 2
#define LL 1024
#define XX 4
#define EE 128
#define YY 4
#define SCALE 0.08838834764831845f   // 1/sqrt(128)

typedef unsigned short ushort_t;

// ---------------- scratch (static device globals) --------------------------
__device__ float g_search[8*1024*1024];                 // stage1 scores fp32; reused as catt partials
__device__ float g_s2    [2*10*1024*1024];              // stage2 scores fp32  80 MB
__device__ float g_vpart [BB*LL*EE*XX];                 // [b][l][e][x]         4 MB

__device__ __align__(16) ushort_t g_qh [2*1024*4*128], g_ql [2*1024*4*128];
__device__ __align__(16) ushort_t g_kh [2*1024*4*128], g_kl [2*1024*4*128];
__device__ __align__(16) ushort_t g_vh [2*1024*512],   g_vl [2*1024*512];
__device__ __align__(16) ushort_t g_qph[2*1024*4*128], g_qpl[2*1024*4*128];
__device__ __align__(16) ushort_t g_wkh[128*128],      g_wkl[128*128];
__device__ __align__(16) ushort_t g_sh [8*1024*1024],  g_sl [8*1024*1024];   // Search bf16
__device__ __align__(16) ushort_t g_qkh[2*1024*4*128], g_qkl[2*1024*4*128];
__device__ __align__(16) ushort_t g_rh [2*4*4*1024*128], g_rl[2*4*4*1024*128];
__device__ __align__(16) ushort_t g_s2h[2*10*1024*1024], g_s2l[2*10*1024*1024];

__constant__ int c_xy_x[10] = {0,1,1,2,2,2,3,3,3,3};
__constant__ int c_xy_y[10] = {0,0,1,0,1,2,0,1,2,3};
__constant__ int c_tri[4]  = {0,1,3,6};

// libdevice path — bit-matches jax-on-GPU reference. DO NOT CHANGE.
__device__ __forceinline__ float sig_transform(float v) {
    float t = 5.0f * v;
    float e = expf(-t);
    float sigmoid = 1.0f / (1.0f + e);
    float sg = sigmoid + 1e-5f;
    float p = powf(3.0f, sg);
    return p - 1.0f;
}

// ================= bf16 split helpers =======================================
__device__ __forceinline__ unsigned bfbits(float x) {
    unsigned u = __float_as_uint(x);
    return (u + 0x7fffu + ((u >> 16) & 1u)) >> 16;
}
__device__ __forceinline__ float bfval(unsigned b) { return __uint_as_float(b << 16); }
__device__ __forceinline__ void split_pack(float x0, float x1, unsigned &hi, unsigned &lo) {
    unsigned h0 = bfbits(x0), h1 = bfbits(x1);
    unsigned l0 = bfbits(x0 - bfval(h0)), l1 = bfbits(x1 - bfval(h1));
    hi = h0 | (h1 << 16);
    lo = l0 | (l1 << 16);
}
__device__ __forceinline__ void mma_bf16(float (&c)[4],
    unsigned a0, unsigned a1, unsigned a2, unsigned a3,
    unsigned b0, unsigned b1)
{
    asm volatile("mma.sync.aligned.m16n8k16.row.col.f32.bf16.bf16.f32 "
        "{%0,%1,%2,%3},{%4,%5,%6,%7},{%8,%9},{%0,%1,%2,%3};"
        : "+f"(c[0]), "+f"(c[1]), "+f"(c[2]), "+f"(c[3])
        : "r"(a0), "r"(a1), "r"(a2), "r"(a3), "r"(b0), "r"(b1));
}
__device__ __forceinline__ void ldsm_x4(unsigned &r0, unsigned &r1,
                                        unsigned &r2, unsigned &r3, unsigned addr)
{
    asm volatile("ldmatrix.sync.aligned.m8n8.x4.shared.b16 {%0,%1,%2,%3}, [%4];"
        : "=r"(r0), "=r"(r1), "=r"(r2), "=r"(r3) : "r"(addr));
}
__device__ __forceinline__ void ldsm_x4t(unsigned &r0, unsigned &r1,
                                         unsigned &r2, unsigned &r3, unsigned addr)
{
    asm volatile("ldmatrix.sync.aligned.m8n8.x4.trans.shared.b16 {%0,%1,%2,%3}, [%4];"
        : "=r"(r0), "=r"(r1), "=r"(r2), "=r"(r3) : "r"(addr));
}
__device__ __forceinline__ void cp_async16(void* dst, const void* src) {
    unsigned s = (unsigned)__cvta_generic_to_shared(dst);
    asm volatile("cp.async.cg.shared.global [%0], [%1], 16;" :: "r"(s), "l"(src));
}
#define CP_COMMIT() asm volatile("cp.async.commit_group;")
template<int N>
__device__ __forceinline__ void cp_wait() {
    asm volatile("cp.async.wait_group %0;" :: "n"(N));
}

// C tile 128x64, 256 threads (8 warps = 4x2 grid of 32x32 warp tiles).
// Operands pre-split bf16 hi/lo in gmem; lda/ldb in bf16 elements.
// TRANSB=0: B is [n][k] (NT). TRANSB=1: B is [k][n] (NN, via ldmatrix.trans).
// 2-stage cp.async double buffer (dynamic smem, 2 * 30 KB).
template<int TRANSB>
__device__ __forceinline__ void mma_core(
    unsigned* __restrict__ SM_,
    const ushort_t* __restrict__ Ahg, const ushort_t* __restrict__ Alg, int lda,
    const ushort_t* __restrict__ Bhg, const ushort_t* __restrict__ Blg, int ldb,
    int K, float (&acc)[2][4][4])
{
    const int tid = threadIdx.x;
    const int lane = tid & 31, w = tid >> 5;
    const int wrow = w >> 1, wcol = w & 1;
    const int lm = lane & 15, lq = lane >> 4;

    const int ar = tid >> 1, ax = tid & 1;    // A staging: 2 thr/row, 16 ushort each
    const int br = tid >> 2, bq = tid & 3;    // B NT: 4 thr/row, 8 ushort each
    const int half = tid >> 7, t7 = tid & 127;
    const int nr = t7 >> 2, nq = t7 & 3;      // B NN: per plane-half, 16 ushort each

    auto prefetch = [&](int kk, int s) {
        unsigned* SA = SM_ + s * 7680;
        unsigned* SB = SA + 5120;
        const ushort_t* pa = Ahg + (size_t)ar*lda + kk + ax*16;
        const ushort_t* pl = Alg + (size_t)ar*lda + kk + ax*16;
        cp_async16(&SA[ar*20 + ax*8],            pa);
        cp_async16(&SA[ar*20 + ax*8 + 4],        pa + 8);
        cp_async16(&SA[2560 + ar*20 + ax*8],     pl);
        cp_async16(&SA[2560 + ar*20 + ax*8 + 4], pl + 8);
        if (TRANSB) {
            const ushort_t* pb = (half ? Blg : Bhg) + (size_t)(kk + nr)*ldb + nq*16;
            ushort_t* bd = (ushort_t*)(SB + half*1280) + nr*72 + nq*16;
            cp_async16(bd,     pb);
            cp_async16(bd + 8, pb + 8);
        } else {
            cp_async16(&SB[br*20 + bq*4],        Bhg + (size_t)br*ldb + kk + bq*8);
            cp_async16(&SB[1280 + br*20 + bq*4], Blg + (size_t)br*ldb + kk + bq*8);
        }
    };

    const int nck = K >> 5;
    prefetch(0, 0); CP_COMMIT();
    for (int c = 0; c < nck; c++) {
        if (c + 1 < nck) { prefetch((c+1) << 5, (c+1) & 1); CP_COMMIT(); cp_wait<1>(); }
        else             { cp_wait<0>(); }
        __syncthreads();
        unsigned* SA = SM_ + (c & 1) * 7680;
        unsigned* SB = SA + 5120;
#pragma unroll
        for (int k16 = 0; k16 < 2; k16++) {
            const int ko = k16*8;
            unsigned ah[2][4], al[2][4], bh[4][2], bl[4][2];
#pragma unroll
            for (int mt = 0; mt < 2; mt++) {
                int m = wrow*32 + mt*16;
                unsigned aw = (unsigned)__cvta_generic_to_shared(
                    &SA[(m + lm)*20 + ko + (lq<<2)]);
                ldsm_x4(ah[mt][0], ah[mt][1], ah[mt][2], ah[mt][3], aw);
                ldsm_x4(al[mt][0], al[mt][1], al[mt][2], al[mt][3], aw + 2560*4);
            }
#pragma unroll
            for (int p = 0; p < 2; p++) {
                int n0 = wcol*32 + p*16;
                if (TRANSB) {
                    const ushort_t* bb = (const ushort_t*)SB;
                    unsigned bw = (unsigned)__cvta_generic_to_shared(
                        bb + (k16*16 + lm)*72 + n0 + (lq<<3));
                    ldsm_x4t(bh[2*p][0], bh[2*p][1], bh[2*p+1][0], bh[2*p+1][1], bw);
                    ldsm_x4t(bl[2*p][0], bl[2*p][1], bl[2*p+1][0], bl[2*p+1][1], bw + 1280*4);
                } else {
                    unsigned bw = (unsigned)__cvta_generic_to_shared(
                        &SB[(n0 + lm)*20 + ko + (lq<<2)]);
                    ldsm_x4(bh[2*p][0], bh[2*p+1][0], bh[2*p][1], bh[2*p+1][1], bw);
                    ldsm_x4(bl[2*p][0], bl[2*p+1][0], bl[2*p][1], bl[2*p+1][1], bw + 1280*4);
                }
            }
#pragma unroll
            for (int mt = 0; mt < 2; mt++)
#pragma unroll
                for (int nt = 0; nt < 4; nt++) {
                    mma_bf16(acc[mt][nt], ah[mt][0],ah[mt][1],ah[mt][2],ah[mt][3], bh[nt][0],bh[nt][1]);
                    mma_bf16(acc[mt][nt], ah[mt][0],ah[mt][1],ah[mt][2],ah[mt][3], bl[nt][0],bl[nt][1]);
                    mma_bf16(acc[mt][nt], al[mt][0],al[mt][1],al[mt][2],al[mt][3], bh[nt][0],bh[nt][1]);
                }
        }
        __syncthreads();
    }
}

#define SMEM_MMA (2*7680*4)   // 61440 bytes -> 3 blocks/SM

__device__ __forceinline__ void epilogue_f32(
    float (&acc)[2][4][4], float* C, int ldc, float scale)
{
    const int lane = threadIdx.x & 31, w = threadIdx.x >> 5;
    const int g = lane >> 2, tg = lane & 3;
    const int wrow = w >> 1, wcol = w & 1;
#pragma unroll
    for (int mt = 0; mt < 2; mt++)
#pragma unroll
        for (int nt = 0; nt < 4; nt++) {
            int r0 = wrow*32 + mt*16 + g;
            int c0 = wcol*32 + nt*8 + 2*tg;
            float2 v0 = {acc[mt][nt][0]*scale, acc[mt][nt][1]*scale};
            float2 v1 = {acc[mt][nt][2]*scale, acc[mt][nt][3]*scale};
            *(float2*)(C + (size_t)r0*ldc + c0) = v0;
            *(float2*)(C + (size_t)(r0+8)*ldc + c0) = v1;
        }
}

__device__ __forceinline__ void epilogue_bf16(
    float (&acc)[2][4][4], ushort_t* Ch, ushort_t* Cl, int ldc)
{
    const int lane = threadIdx.x & 31, w = threadIdx.x >> 5;
    const int g = lane >> 2, tg = lane & 3;
    const int wrow = w >> 1, wcol = w & 1;
#pragma unroll
    for (int mt = 0; mt < 2; mt++)
#pragma unroll
        for (int nt = 0; nt < 4; nt++) {
            int r0 = wrow*32 + mt*16 + g;
            int c0 = wcol*32 + nt*8 + 2*tg;
            unsigned h, l;
            split_pack(acc[mt][nt][0], acc[mt][nt][1], h, l);
            *(unsigned*)(Ch + (size_t)r0*ldc + c0) = h;
            *(unsigned*)(Cl + (size_t)r0*ldc + c0) = l;
            split_pack(acc[mt][nt][2], acc[mt][nt][3], h, l);
            *(unsigned*)(Ch + (size_t)(r0+8)*ldc + c0) = h;
            *(unsigned*)(Cl + (size_t)(r0+8)*ldc + c0) = l;
        }
}

// ---------------- fp32 NT core (vout only) ---------------------------------
__device__ __forceinline__ void gemm_nt_core(
    const float* __restrict__ A, int lda,
    const float* __restrict__ B, int ldb,
    float* __restrict__ C, int ldc,
    int K, float scale, const float* __restrict__ bias)
{
    __shared__ float As[16*68];
    __shared__ float Bs[16*68];
    const int tid = threadIdx.x;
    const int tx = tid & 15, ty = tid >> 4;
    const int lr = tid >> 2;
    const int lk = (tid & 3) << 2;
    const int row0 = blockIdx.y * 64;
    const int col0 = blockIdx.x * 64;
    const float* Ap = A + (size_t)(row0 + lr) * lda + lk;
    const float* Bp = B + (size_t)(col0 + lr) * ldb + lk;
    float acc[4][4] = {};
    for (int kk = 0; kk < K; kk += 16) {
        float4 av = *(const float4*)(Ap + kk);
        float4 bv = *(const float4*)(Bp + kk);
        __syncthreads();
        As[(lk+0)*68+lr]=av.x; As[(lk+1)*68+lr]=av.y;
        As[(lk+2)*68+lr]=av.z; As[(lk+3)*68+lr]=av.w;
        Bs[(lk+0)*68+lr]=bv.x; Bs[(lk+1)*68+lr]=bv.y;
        Bs[(lk+2)*68+lr]=bv.z; Bs[(lk+3)*68+lr]=bv.w;
        __syncthreads();
#pragma unroll
        for (int k = 0; k < 16; k++) {
            float4 a4 = *(const float4*)&As[k*68 + ty*4];
            float4 b4 = *(const float4*)&Bs[k*68 + tx*4];
            float a_[4] = {a4.x, a4.y, a4.z, a4.w};
            float b_[4] = {b4.x, b4.y, b4.z, b4.w};
#pragma unroll
            for (int i = 0; i < 4; i++)
#pragma unroll
                for (int j = 0; j < 4; j++)
                    acc[i][j] = fmaf(a_[i], b_[j], acc[i][j]);
        }
    }
#pragma unroll
    for (int i = 0; i < 4; i++) {
        float4 o;
        o.x = acc[i][0]*scale + bias[col0+tx*4+0];
        o.y = acc[i][1]*scale + bias[col0+tx*4+1];
        o.z = acc[i][2]*scale + bias[col0+tx*4+2];
        o.w = acc[i][3]*scale + bias[col0+tx*4+3];
        *(float4*)&C[(size_t)(row0+ty*4+i)*ldc + col0 + tx*4] = o;
    }
}

// ================= kernels ==================================================

// split fp32 inputs -> bf16 hi/lo
__global__ void __launch_bounds__(256) aa_cvt(
    const float* __restrict__ q, const float* __restrict__ k,
    const float* __restrict__ val, const float* __restrict__ qp,
    const float* __restrict__ Wk)
{
    const float* src; ushort_t *dh, *dl; int n;
    switch (blockIdx.y) {
        case 0: src = q;   dh = g_qh;  dl = g_ql;  n = 1048576; break;
        case 1: src = k;   dh = g_kh;  dl = g_kl;  n = 1048576; break;
        case 2: src = val; dh = g_vh;  dl = g_vl;  n = 1048576; break;
        case 3: src = qp;  dh = g_qph; dl = g_qpl; n = 1048576; break;
        default:src = Wk;  dh = g_wkh; dl = g_wkl; n = 16384;   break;
    }
    int i = (blockIdx.x * 256 + threadIdx.x) * 4;
    if (i >= n) return;
    float4 v = *(const float4*)(src + i);
    unsigned h0,l0,h1,l1;
    split_pack(v.x, v.y, h0, l0);
    split_pack(v.z, v.w, h1, l1);
    *(uint2*)(dh + i) = make_uint2(h0, h1);
    *(uint2*)(dl + i) = make_uint2(l0, l1);
}

// stage 1 scores: g_search = scale * Q K^T
__global__ void __launch_bounds__(256, 3) aa_t_scores1()
{
    extern __shared__ unsigned smx[];
    int bz = blockIdx.z, b = bz >> 2, x = bz & 3;
    size_t qoff = (size_t)b*524288 + x*128;
    const ushort_t* Ah = g_qh + qoff + (size_t)blockIdx.y*128*512;
    const ushort_t* Al = g_ql + qoff + (size_t)blockIdx.y*128*512;
    const ushort_t* Bh = g_kh + qoff + (size_t)blockIdx.x*64*512;
    const ushort_t* Bl = g_kl + qoff + (size_t)blockIdx.x*64*512;
    float acc[2][4][4] = {};
    mma_core<0>(smx, Ah, Al, 512, Bh, Bl, 512, 128, acc);
    float* C = g_search + (size_t)bz*1048576 + (size_t)blockIdx.y*128*1024 + blockIdx.x*64;
    epilogue_f32(acc, C, 1024, SCALE);
}

// row softmax over s; emits bf16 hi/lo Search
__global__ void __launch_bounds__(256) aa_k_softmax()
{
    size_t row = blockIdx.x;
    const float* p = g_search + row * 1024;
    int tid = threadIdx.x;
    float4 v4 = *(const float4*)(p + tid*4);
    float v[4] = {v4.x, v4.y, v4.z, v4.w};
    float m = fmaxf(fmaxf(v[0], v[1]), fmaxf(v[2], v[3]));
    __shared__ float red[256];
    red[tid] = m; __syncthreads();
    for (int s = 128; s > 0; s >>= 1) {
        if (tid < s) red[tid] = fmaxf(red[tid], red[tid+s]);
        __syncthreads();
    }
    m = red[0]; __syncthreads();
    float sum = 0.f;
#pragma unroll
    for (int i = 0; i < 4; i++) { v[i] = expf(v[i] - m); sum += v[i]; }
    red[tid] = sum; __syncthreads();
    for (int s = 128; s > 0; s >>= 1) {
        if (tid < s) red[tid] += red[tid+s];
        __syncthreads();
    }
    float inv = 1.f / red[0];
    unsigned h0,l0,h1,l1;
    split_pack(v[0]*inv, v[1]*inv, h0, l0);
    split_pack(v[2]*inv, v[3]*inv, h1, l1);
    *(uint2*)(g_sh + row*1024 + tid*4) = make_uint2(h0, h1);
    *(uint2*)(g_sl + row*1024 + tid*4) = make_uint2(l0, l1);
}

// Retrieval planes (NN): out bf16 hi/lo g_r[plane][m][e]
// grid (2 n-halves, 8 m-tiles, 20 planes) — no dead blocks
__global__ void __launch_bounds__(256, 3) aa_t_retr()
{
    extern __shared__ unsigned smx[];
    int t = blockIdx.z, b = t / 10, u = t % 10;
    int x = c_xy_x[u], y = c_xy_y[u];
    int bz = b*4 + x;
    int n0 = y*128 + blockIdx.x*64;
    const ushort_t* Ah = g_sh + (size_t)bz*1048576 + (size_t)blockIdx.y*128*1024;
    const ushort_t* Al = g_sl + (size_t)bz*1048576 + (size_t)blockIdx.y*128*1024;
    const ushort_t* Bh = g_vh + (size_t)b*524288 + n0;
    const ushort_t* Bl = g_vl + (size_t)b*524288 + n0;
    float acc[2][4][4] = {};
    mma_core<1>(smx, Ah, Al, 1024, Bh, Bl, 512, 1024, acc);
    size_t coff = ((size_t)(bz*4 + y))*131072 + (size_t)blockIdx.y*128*128 + blockIdx.x*64;
    epilogue_bf16(acc, g_rh + coff, g_rl + coff, 128);
}

// qk = q_plus @ Wk (NN, bias cancels in softmax) -> bf16 hi/lo
__global__ void __launch_bounds__(256, 3) aa_t_qk()
{
    extern __shared__ unsigned smx[];
    const ushort_t* Ah = g_qph + (size_t)blockIdx.y*128*128;
    const ushort_t* Al = g_qpl + (size_t)blockIdx.y*128*128;
    float acc[2][4][4] = {};
    mma_core<1>(smx, Ah, Al, 128, g_wkh + blockIdx.x*64, g_wkl + blockIdx.x*64, 128, 128, acc);
    size_t coff = (size_t)blockIdx.y*128*128 + blockIdx.x*64;
    epilogue_bf16(acc, g_qkh + coff, g_qkl + coff, 128);
}

// stage-2 scores planes (NT): g_s2[plane] = scale * qk · R^T
__global__ void __launch_bounds__(256, 3) aa_t_scores2()
{
    extern __shared__ unsigned smx[];
    int t = blockIdx.z, b = t / 10, u = t % 10;
    int x = c_xy_x[u], y = c_xy_y[u];
    size_t aoff = (size_t)b*524288 + x*128 + (size_t)blockIdx.y*128*512;
    size_t boff = ((size_t)((b*4 + x)*4 + y))*131072 + (size_t)blockIdx.x*64*128;
    float acc[2][4][4] = {};
    mma_core<0>(smx, g_qkh + aoff, g_qkl + aoff, 512, g_rh + boff, g_rl + boff, 128, 128, acc);
    float* C = g_s2 + ((size_t)(b*10 + u))*1048576
             + (size_t)blockIdx.y*128*1024 + blockIdx.x*64;
    epilogue_f32(acc, C, 1024, SCALE);
}

// softmax over y across planes -> series bf16 hi/lo
__global__ void __launch_bounds__(256) aa_k_softmax2()
{
    int blk = blockIdx.x;
    int l = blk & 1023;
    int x = (blk >> 10) & 3;
    int b = blk >> 12;
    int ny = x + 1;
    size_t pbase = ((size_t)(b*10 + c_tri[x]))*1048576 + (size_t)l*1024 + threadIdx.x*4;
    float4 v[4];
#pragma unroll
    for (int y = 0; y < 4; y++)
        if (y < ny) v[y] = *(const float4*)(g_s2 + pbase + (size_t)y*1048576);
        else        v[y] = make_float4(-1e30f,-1e30f,-1e30f,-1e30f);
    float4 mx;
    mx.x = fmaxf(fmaxf(v[0].x,v[1].x), fmaxf(v[2].x,v[3].x));
    mx.y = fmaxf(fmaxf(v[0].y,v[1].y), fmaxf(v[2].y,v[3].y));
    mx.z = fmaxf(fmaxf(v[0].z,v[1].z), fmaxf(v[2].z,v[3].z));
    mx.w = fmaxf(fmaxf(v[0].w,v[1].w), fmaxf(v[2].w,v[3].w));
    float4 s = make_float4(0,0,0,0);
#pragma unroll
    for (int y = 0; y < 4; y++) {
        if (y < ny) {
            v[y].x = expf(v[y].x - mx.x); s.x += v[y].x;
            v[y].y = expf(v[y].y - mx.y); s.y += v[y].y;
            v[y].z = expf(v[y].z - mx.z); s.z += v[y].z;
            v[y].w = expf(v[y].w - mx.w); s.w += v[y].w;
        }
    }
    float4 inv = make_float4(1.f/s.x, 1.f/s.y, 1.f/s.z, 1.f/s.w);
#pragma unroll
    for (int y = 0; y < 4; y++) {
        if (y < ny) {
            unsigned h0,l0,h1,l1;
            split_pack(v[y].x*inv.x, v[y].y*inv.y, h0, l0);
            split_pack(v[y].z*inv.z, v[y].w*inv.w, h1, l1);
            *(uint2*)(g_s2h + pbase + (size_t)y*1048576) = make_uint2(h0, h1);
            *(uint2*)(g_s2l + pbase + (size_t)y*1048576) = make_uint2(l0, l1);
        }
    }
}

// catt partials (NN): P[plane][l][e] = series_plane @ R_plane, one plane per block-z.
// grid (2 e-halves, 8 l-tiles, 20 planes) — uniform K=1024, fully balanced.
// Partials stored in g_search (free after softmax1).
__global__ void __launch_bounds__(256, 3) aa_t_catt()
{
    extern __shared__ unsigned smx[];
    int t = blockIdx.z, b = t / 10, u = t % 10;
    int x = c_xy_x[u], y = c_xy_y[u];
    size_t aoff = ((size_t)(b*10 + u))*1048576 + (size_t)blockIdx.y*128*1024;
    size_t boff = ((size_t)((b*4 + x)*4 + y))*131072 + blockIdx.x*64;
    float acc[2][4][4] = {};
    mma_core<1>(smx, g_s2h + aoff, g_s2l + aoff, 1024, g_rh + boff, g_rl + boff, 128, 1024, acc);
    float* P = g_search + (size_t)t*131072
             + (size_t)blockIdx.y*128*128 + blockIdx.x*64;
    epilogue_f32(acc, P, 128, 1.0f);
}

// reduce partials over y: g_vpart[b][l][e][x] = sum_y P[(b,x,y)][l][e]
__global__ void __launch_bounds__(256) aa_k_vred()
{
    int i = blockIdx.x * 256 + threadIdx.x;   // (b,x,l,e), e fastest
    int e = i & 127;
    int l = (i >> 7) & 1023;
    int x = (i >> 17) & 3;
    int b = i >> 19;
    int ny = x + 1;
    size_t p0 = ((size_t)(b*10 + c_tri[x]))*131072 + (size_t)l*128 + e;
    float s = 0.f;
    for (int y = 0; y < ny; y++) s += g_search[p0 + (size_t)y*131072];
    g_vpart[(((size_t)b*1024 + l)*128 + e)*4 + x] = s;
}

// V output: g_vpart (viewed [8192,128]) @ Wv^T + bv — fp32, tiny
__global__ void __launch_bounds__(256) aa_k_vout(const float* __restrict__ Wv,
                                                 const float* __restrict__ bv,
                                                 float* __restrict__ out)
{
    gemm_nt_core(g_vpart, EE, Wv, EE, out, EE, EE, 1.0f, bv);
}

// series_out == 0.25 everywhere (float4)
__global__ void __launch_bounds__(256) aa_k_fill(float4* __restrict__ p, float v)
{
    p[(size_t)blockIdx.x * 256 + threadIdx.x] = make_float4(v, v, v, v);
}

// prior + sig (bit-exact libdevice path — DO NOT CHANGE)
__global__ void __launch_bounds__(256) aa_k_prior(const float* __restrict__ sigma,
                                                  float* __restrict__ prior,
                                                  float* __restrict__ sig_out)
{
    int row = blockIdx.x;
    int i = row & 1023;
    int h = (row >> 10) & 3;
    int b = row >> 12;
    float v = sigma[((size_t)b*LL + i)*XX + h];
    float s = sig_transform(v);
    if (threadIdx.x == 0) sig_out[row] = s;
    float denom = 2.5066282746310002f * s;
    float coef = 1.0f / denom;
    float s2 = s * s;
    float* p = prior + (size_t)row * LL;
    float fi = (float)i;
    for (int j = threadIdx.x; j < LL; j += 256) {
        float d = fabsf(fi - (float)j);
        float d2 = d * d;
        float num = -d2 * 0.5f;
        float arg = num / s2;
        p[j] = coef * expf(arg);
    }
}

// =========================================================================
extern "C" void kernel_launch(void* const* d_in, const int* in_sizes, int n_in,
                              void* d_out, int out_size)
{
    const float* big[5] = {};
    int nbig = 0;
    const float* sigma = nullptr;
    const float* w[2] = {};
    int nw = 0;
    const float* bias[2] = {};
    int nb = 0;
    for (int i = 0; i < n_in; i++) {
        int sz = in_sizes[i];
        if (sz == BB*LL*XX*EE)      { if (nbig < 5) big[nbig++] = (const float*)d_in[i]; }
        else if (sz == BB*LL*XX)    { sigma = (const float*)d_in[i]; }
        else if (sz == EE*EE)       { if (nw < 2) w[nw++] = (const float*)d_in[i]; }
        else if (sz == EE)          { if (nb < 2) bias[nb++] = (const float*)d_in[i]; }
    }
    const float* query = big[1];
    const float* key_  = big[2];
    const float* value = big[3];
    const float* qplus = big[4];
    const float* Wk = w[0];
    const float* Wv = w[1];    const float* bv = bias[1];

    float* out       = (float*)d_out;
    float* outV      = out;
    float* outSeries = out + 1048576;
    float* outPrior  = out + 1048576 + 8388608;
    float* outSig    = out + 1048576 + 2*8388608;

    static int smem_set = 0;
    if (!smem_set) {
        cudaFuncSetAttribute(aa_t_scores1, cudaFuncAttributeMaxDynamicSharedMemorySize, SMEM_MMA);
        cudaFuncSetAttribute(aa_t_retr,    cudaFuncAttributeMaxDynamicSharedMemorySize, SMEM_MMA);
        cudaFuncSetAttribute(aa_t_qk,      cudaFuncAttributeMaxDynamicSharedMemorySize, SMEM_MMA);
        cudaFuncSetAttribute(aa_t_scores2, cudaFuncAttributeMaxDynamicSharedMemorySize, SMEM_MMA);
        cudaFuncSetAttribute(aa_t_catt,    cudaFuncAttributeMaxDynamicSharedMemorySize, SMEM_MMA);
        smem_set = 1;
    }

    dim3 thr(256);
    aa_cvt      <<<dim3(1024,5),   thr>>>(query, key_, value, qplus, Wk);
    aa_t_scores1<<<dim3(16,8,8),   thr, SMEM_MMA>>>();
    aa_k_softmax<<<dim3(8192),     thr>>>();
    aa_t_retr   <<<dim3(2,8,20),   thr, SMEM_MMA>>>();
    aa_t_qk     <<<dim3(2,64),     thr, SMEM_MMA>>>();
    aa_t_scores2<<<dim3(16,8,20),  thr, SMEM_MMA>>>();
    aa_k_softmax2<<<dim3(8192),    thr>>>();
    aa_t_catt   <<<dim3(2,8,20),   thr, SMEM_MMA>>>();
    aa_k_vred   <<<dim3(4096),     thr>>>();
    aa_k_vout   <<<dim3(2,128),    thr>>>(Wv, bv, outV);
    aa_k_fill   <<<dim3(8192),     thr>>>((float4*)outSeries, 0.25f);
    aa_k_prior  <<<dim3(8192),     thr>>>(sigma, outPrior, outSig);
}

// round 16
// speedup vs baseline: 1.1940x; 1.0190x over previous
#include <cuda_runtime.h>
#include <math.h>

#define BB 2
#define LL 1024
#define XX 4
#define EE 128
#define YY 4
#define SCALE 0.08838834764831845f   // 1/sqrt(128)

typedef unsigned short ushort_t;

// ---------------- scratch (static device globals) --------------------------
__device__ float g_search[8*1024*1024];                 // stage1 scores fp32; reused as catt partials
__device__ float g_s2    [2*10*1024*1024];              // stage2 scores fp32  80 MB
__device__ float g_vpart [BB*LL*EE*XX];                 // [b][l][e][x]         4 MB

__device__ __align__(16) ushort_t g_qh [2*1024*4*128], g_ql [2*1024*4*128];
__device__ __align__(16) ushort_t g_kh [2*1024*4*128], g_kl [2*1024*4*128];
__device__ __align__(16) ushort_t g_vh [2*1024*512],   g_vl [2*1024*512];
__device__ __align__(16) ushort_t g_qph[2*1024*4*128], g_qpl[2*1024*4*128];
__device__ __align__(16) ushort_t g_wkh[128*128],      g_wkl[128*128];
__device__ __align__(16) ushort_t g_sh [8*1024*1024],  g_sl [8*1024*1024];   // Search bf16
__device__ __align__(16) ushort_t g_qkh[2*1024*4*128], g_qkl[2*1024*4*128];
__device__ __align__(16) ushort_t g_rh [2*4*4*1024*128], g_rl[2*4*4*1024*128];
__device__ __align__(16) ushort_t g_s2h[2*10*1024*1024], g_s2l[2*10*1024*1024];

__constant__ int c_xy_x[10] = {0,1,1,2,2,2,3,3,3,3};
__constant__ int c_xy_y[10] = {0,0,1,0,1,2,0,1,2,3};
__constant__ int c_tri[4]  = {0,1,3,6};

// libdevice path — bit-matches jax-on-GPU reference. DO NOT CHANGE.
__device__ __forceinline__ float sig_transform(float v) {
    float t = 5.0f * v;
    float e = expf(-t);
    float sigmoid = 1.0f / (1.0f + e);
    float sg = sigmoid + 1e-5f;
    float p = powf(3.0f, sg);
    return p - 1.0f;
}

// ================= bf16 split helpers =======================================
__device__ __forceinline__ unsigned bfbits(float x) {
    unsigned u = __float_as_uint(x);
    return (u + 0x7fffu + ((u >> 16) & 1u)) >> 16;
}
__device__ __forceinline__ float bfval(unsigned b) { return __uint_as_float(b << 16); }
__device__ __forceinline__ void split_pack(float x0, float x1, unsigned &hi, unsigned &lo) {
    unsigned h0 = bfbits(x0), h1 = bfbits(x1);
    unsigned l0 = bfbits(x0 - bfval(h0)), l1 = bfbits(x1 - bfval(h1));
    hi = h0 | (h1 << 16);
    lo = l0 | (l1 << 16);
}
__device__ __forceinline__ void mma_bf16(float (&c)[4],
    unsigned a0, unsigned a1, unsigned a2, unsigned a3,
    unsigned b0, unsigned b1)
{
    asm volatile("mma.sync.aligned.m16n8k16.row.col.f32.bf16.bf16.f32 "
        "{%0,%1,%2,%3},{%4,%5,%6,%7},{%8,%9},{%0,%1,%2,%3};"
        : "+f"(c[0]), "+f"(c[1]), "+f"(c[2]), "+f"(c[3])
        : "r"(a0), "r"(a1), "r"(a2), "r"(a3), "r"(b0), "r"(b1));
}
__device__ __forceinline__ void ldsm_x4(unsigned &r0, unsigned &r1,
                                        unsigned &r2, unsigned &r3, unsigned addr)
{
    asm volatile("ldmatrix.sync.aligned.m8n8.x4.shared.b16 {%0,%1,%2,%3}, [%4];"
        : "=r"(r0), "=r"(r1), "=r"(r2), "=r"(r3) : "r"(addr));
}
__device__ __forceinline__ void ldsm_x4t(unsigned &r0, unsigned &r1,
                                         unsigned &r2, unsigned &r3, unsigned addr)
{
    asm volatile("ldmatrix.sync.aligned.m8n8.x4.trans.shared.b16 {%0,%1,%2,%3}, [%4];"
        : "=r"(r0), "=r"(r1), "=r"(r2), "=r"(r3) : "r"(addr));
}
__device__ __forceinline__ void cp_async16(void* dst, const void* src) {
    unsigned s = (unsigned)__cvta_generic_to_shared(dst);
    asm volatile("cp.async.cg.shared.global [%0], [%1], 16;" :: "r"(s), "l"(src));
}
#define CP_COMMIT() asm volatile("cp.async.commit_group;")
template<int N>
__device__ __forceinline__ void cp_wait() {
    asm volatile("cp.async.wait_group %0;" :: "n"(N));
}

// C tile 128x64, 256 threads (8 warps = 4x2 grid of 32x32 warp tiles).
// Operands pre-split bf16 hi/lo in gmem; lda/ldb in bf16 elements.
// TRANSB=0: B is [n][k] (NT). TRANSB=1: B is [k][n] (NN, via ldmatrix.trans).
// 2-stage cp.async double buffer (dynamic smem, 2 * 30 KB).
template<int TRANSB>
__device__ __forceinline__ void mma_core(
    unsigned* __restrict__ SM_,
    const ushort_t* __restrict__ Ahg, const ushort_t* __restrict__ Alg, int lda,
    const ushort_t* __restrict__ Bhg, const ushort_t* __restrict__ Blg, int ldb,
    int K, float (&acc)[2][4][4])
{
    const int tid = threadIdx.x;
    const int lane = tid & 31, w = tid >> 5;
    const int wrow = w >> 1, wcol = w & 1;
    const int lm = lane & 15, lq = lane >> 4;

    const int ar = tid >> 1, ax = tid & 1;    // A staging: 2 thr/row, 16 ushort each
    const int br = tid >> 2, bq = tid & 3;    // B NT: 4 thr/row, 8 ushort each
    const int half = tid >> 7, t7 = tid & 127;
    const int nr = t7 >> 2, nq = t7 & 3;      // B NN: per plane-half, 16 ushort each

    auto prefetch = [&](int kk, int s) {
        unsigned* SA = SM_ + s * 7680;
        unsigned* SB = SA + 5120;
        const ushort_t* pa = Ahg + (size_t)ar*lda + kk + ax*16;
        const ushort_t* pl = Alg + (size_t)ar*lda + kk + ax*16;
        cp_async16(&SA[ar*20 + ax*8],            pa);
        cp_async16(&SA[ar*20 + ax*8 + 4],        pa + 8);
        cp_async16(&SA[2560 + ar*20 + ax*8],     pl);
        cp_async16(&SA[2560 + ar*20 + ax*8 + 4], pl + 8);
        if (TRANSB) {
            const ushort_t* pb = (half ? Blg : Bhg) + (size_t)(kk + nr)*ldb + nq*16;
            ushort_t* bd = (ushort_t*)(SB + half*1280) + nr*72 + nq*16;
            cp_async16(bd,     pb);
            cp_async16(bd + 8, pb + 8);
        } else {
            cp_async16(&SB[br*20 + bq*4],        Bhg + (size_t)br*ldb + kk + bq*8);
            cp_async16(&SB[1280 + br*20 + bq*4], Blg + (size_t)br*ldb + kk + bq*8);
        }
    };

    const int nck = K >> 5;
    prefetch(0, 0); CP_COMMIT();
    for (int c = 0; c < nck; c++) {
        if (c + 1 < nck) { prefetch((c+1) << 5, (c+1) & 1); CP_COMMIT(); cp_wait<1>(); }
        else             { cp_wait<0>(); }
        __syncthreads();
        unsigned* SA = SM_ + (c & 1) * 7680;
        unsigned* SB = SA + 5120;
#pragma unroll
        for (int k16 = 0; k16 < 2; k16++) {
            const int ko = k16*8;
            unsigned ah[2][4], al[2][4], bh[4][2], bl[4][2];
#pragma unroll
            for (int mt = 0; mt < 2; mt++) {
                int m = wrow*32 + mt*16;
                unsigned aw = (unsigned)__cvta_generic_to_shared(
                    &SA[(m + lm)*20 + ko + (lq<<2)]);
                ldsm_x4(ah[mt][0], ah[mt][1], ah[mt][2], ah[mt][3], aw);
                ldsm_x4(al[mt][0], al[mt][1], al[mt][2], al[mt][3], aw + 2560*4);
            }
#pragma unroll
            for (int p = 0; p < 2; p++) {
                int n0 = wcol*32 + p*16;
                if (TRANSB) {
                    const ushort_t* bb = (const ushort_t*)SB;
                    unsigned bw = (unsigned)__cvta_generic_to_shared(
                        bb + (k16*16 + lm)*72 + n0 + (lq<<3));
                    ldsm_x4t(bh[2*p][0], bh[2*p][1], bh[2*p+1][0], bh[2*p+1][1], bw);
                    ldsm_x4t(bl[2*p][0], bl[2*p][1], bl[2*p+1][0], bl[2*p+1][1], bw + 1280*4);
                } else {
                    unsigned bw = (unsigned)__cvta_generic_to_shared(
                        &SB[(n0 + lm)*20 + ko + (lq<<2)]);
                    ldsm_x4(bh[2*p][0], bh[2*p+1][0], bh[2*p][1], bh[2*p+1][1], bw);
                    ldsm_x4(bl[2*p][0], bl[2*p+1][0], bl[2*p][1], bl[2*p+1][1], bw + 1280*4);
                }
            }
#pragma unroll
            for (int mt = 0; mt < 2; mt++)
#pragma unroll
                for (int nt = 0; nt < 4; nt++) {
                    mma_bf16(acc[mt][nt], ah[mt][0],ah[mt][1],ah[mt][2],ah[mt][3], bh[nt][0],bh[nt][1]);
                    mma_bf16(acc[mt][nt], ah[mt][0],ah[mt][1],ah[mt][2],ah[mt][3], bl[nt][0],bl[nt][1]);
                    mma_bf16(acc[mt][nt], al[mt][0],al[mt][1],al[mt][2],al[mt][3], bh[nt][0],bh[nt][1]);
                }
        }
        __syncthreads();
    }
}

#define SMEM_MMA (2*7680*4)   // 61440 bytes

__device__ __forceinline__ void epilogue_f32(
    float (&acc)[2][4][4], float* C, int ldc, float scale)
{
    const int lane = threadIdx.x & 31, w = threadIdx.x >> 5;
    const int g = lane >> 2, tg = lane & 3;
    const int wrow = w >> 1, wcol = w & 1;
#pragma unroll
    for (int mt = 0; mt < 2; mt++)
#pragma unroll
        for (int nt = 0; nt < 4; nt++) {
            int r0 = wrow*32 + mt*16 + g;
            int c0 = wcol*32 + nt*8 + 2*tg;
            float2 v0 = {acc[mt][nt][0]*scale, acc[mt][nt][1]*scale};
            float2 v1 = {acc[mt][nt][2]*scale, acc[mt][nt][3]*scale};
            *(float2*)(C + (size_t)r0*ldc + c0) = v0;
            *(float2*)(C + (size_t)(r0+8)*ldc + c0) = v1;
        }
}

__device__ __forceinline__ void epilogue_bf16(
    float (&acc)[2][4][4], ushort_t* Ch, ushort_t* Cl, int ldc)
{
    const int lane = threadIdx.x & 31, w = threadIdx.x >> 5;
    const int g = lane >> 2, tg = lane & 3;
    const int wrow = w >> 1, wcol = w & 1;
#pragma unroll
    for (int mt = 0; mt < 2; mt++)
#pragma unroll
        for (int nt = 0; nt < 4; nt++) {
            int r0 = wrow*32 + mt*16 + g;
            int c0 = wcol*32 + nt*8 + 2*tg;
            unsigned h, l;
            split_pack(acc[mt][nt][0], acc[mt][nt][1], h, l);
            *(unsigned*)(Ch + (size_t)r0*ldc + c0) = h;
            *(unsigned*)(Cl + (size_t)r0*ldc + c0) = l;
            split_pack(acc[mt][nt][2], acc[mt][nt][3], h, l);
            *(unsigned*)(Ch + (size_t)(r0+8)*ldc + c0) = h;
            *(unsigned*)(Cl + (size_t)(r0+8)*ldc + c0) = l;
        }
}

// ---------------- fp32 NT core (vout only) ---------------------------------
__device__ __forceinline__ void gemm_nt_core(
    const float* __restrict__ A, int lda,
    const float* __restrict__ B, int ldb,
    float* __restrict__ C, int ldc,
    int K, float scale, const float* __restrict__ bias)
{
    __shared__ float As[16*68];
    __shared__ float Bs[16*68];
    const int tid = threadIdx.x;
    const int tx = tid & 15, ty = tid >> 4;
    const int lr = tid >> 2;
    const int lk = (tid & 3) << 2;
    const int row0 = blockIdx.y * 64;
    const int col0 = blockIdx.x * 64;
    const float* Ap = A + (size_t)(row0 + lr) * lda + lk;
    const float* Bp = B + (size_t)(col0 + lr) * ldb + lk;
    float acc[4][4] = {};
    for (int kk = 0; kk < K; kk += 16) {
        float4 av = *(const float4*)(Ap + kk);
        float4 bv = *(const float4*)(Bp + kk);
        __syncthreads();
        As[(lk+0)*68+lr]=av.x; As[(lk+1)*68+lr]=av.y;
        As[(lk+2)*68+lr]=av.z; As[(lk+3)*68+lr]=av.w;
        Bs[(lk+0)*68+lr]=bv.x; Bs[(lk+1)*68+lr]=bv.y;
        Bs[(lk+2)*68+lr]=bv.z; Bs[(lk+3)*68+lr]=bv.w;
        __syncthreads();
#pragma unroll
        for (int k = 0; k < 16; k++) {
            float4 a4 = *(const float4*)&As[k*68 + ty*4];
            float4 b4 = *(const float4*)&Bs[k*68 + tx*4];
            float a_[4] = {a4.x, a4.y, a4.z, a4.w};
            float b_[4] = {b4.x, b4.y, b4.z, b4.w};
#pragma unroll
            for (int i = 0; i < 4; i++)
#pragma unroll
                for (int j = 0; j < 4; j++)
                    acc[i][j] = fmaf(a_[i], b_[j], acc[i][j]);
        }
    }
#pragma unroll
    for (int i = 0; i < 4; i++) {
        float4 o;
        o.x = acc[i][0]*scale + bias[col0+tx*4+0];
        o.y = acc[i][1]*scale + bias[col0+tx*4+1];
        o.z = acc[i][2]*scale + bias[col0+tx*4+2];
        o.w = acc[i][3]*scale + bias[col0+tx*4+3];
        *(float4*)&C[(size_t)(row0+ty*4+i)*ldc + col0 + tx*4] = o;
    }
}

// ================= kernels ==================================================

// split fp32 inputs -> bf16 hi/lo
__global__ void __launch_bounds__(256) aa_cvt(
    const float* __restrict__ q, const float* __restrict__ k,
    const float* __restrict__ val, const float* __restrict__ qp,
    const float* __restrict__ Wk)
{
    const float* src; ushort_t *dh, *dl; int n;
    switch (blockIdx.y) {
        case 0: src = q;   dh = g_qh;  dl = g_ql;  n = 1048576; break;
        case 1: src = k;   dh = g_kh;  dl = g_kl;  n = 1048576; break;
        case 2: src = val; dh = g_vh;  dl = g_vl;  n = 1048576; break;
        case 3: src = qp;  dh = g_qph; dl = g_qpl; n = 1048576; break;
        default:src = Wk;  dh = g_wkh; dl = g_wkl; n = 16384;   break;
    }
    int i = (blockIdx.x * 256 + threadIdx.x) * 4;
    if (i >= n) return;
    float4 v = *(const float4*)(src + i);
    unsigned h0,l0,h1,l1;
    split_pack(v.x, v.y, h0, l0);
    split_pack(v.z, v.w, h1, l1);
    *(uint2*)(dh + i) = make_uint2(h0, h1);
    *(uint2*)(dl + i) = make_uint2(l0, l1);
}

// stage 1 scores: g_search = scale * Q K^T
__global__ void __launch_bounds__(256, 3) aa_t_scores1()
{
    extern __shared__ unsigned smx[];
    int bz = blockIdx.z, b = bz >> 2, x = bz & 3;
    size_t qoff = (size_t)b*524288 + x*128;
    const ushort_t* Ah = g_qh + qoff + (size_t)blockIdx.y*128*512;
    const ushort_t* Al = g_ql + qoff + (size_t)blockIdx.y*128*512;
    const ushort_t* Bh = g_kh + qoff + (size_t)blockIdx.x*64*512;
    const ushort_t* Bl = g_kl + qoff + (size_t)blockIdx.x*64*512;
    float acc[2][4][4] = {};
    mma_core<0>(smx, Ah, Al, 512, Bh, Bl, 512, 128, acc);
    float* C = g_search + (size_t)bz*1048576 + (size_t)blockIdx.y*128*1024 + blockIdx.x*64;
    epilogue_f32(acc, C, 1024, SCALE);
}

// row softmax over s; emits bf16 hi/lo Search (shuffle reduction + __expf)
__global__ void __launch_bounds__(256) aa_k_softmax()
{
    size_t row = blockIdx.x;
    const float* p = g_search + row * 1024;
    int tid = threadIdx.x;
    int lane = tid & 31, wid = tid >> 5;
    float4 v4 = *(const float4*)(p + tid*4);
    float v[4] = {v4.x, v4.y, v4.z, v4.w};
    float m = fmaxf(fmaxf(v[0], v[1]), fmaxf(v[2], v[3]));
#pragma unroll
    for (int o = 16; o > 0; o >>= 1) m = fmaxf(m, __shfl_xor_sync(~0u, m, o));
    __shared__ float red[8];
    if (lane == 0) red[wid] = m;
    __syncthreads();
    m = red[0];
#pragma unroll
    for (int i = 1; i < 8; i++) m = fmaxf(m, red[i]);
    float sum = 0.f;
#pragma unroll
    for (int i = 0; i < 4; i++) { v[i] = __expf(v[i] - m); sum += v[i]; }
#pragma unroll
    for (int o = 16; o > 0; o >>= 1) sum += __shfl_xor_sync(~0u, sum, o);
    __syncthreads();
    if (lane == 0) red[wid] = sum;
    __syncthreads();
    sum = red[0];
#pragma unroll
    for (int i = 1; i < 8; i++) sum += red[i];
    float inv = 1.f / sum;
    unsigned h0,l0,h1,l1;
    split_pack(v[0]*inv, v[1]*inv, h0, l0);
    split_pack(v[2]*inv, v[3]*inv, h1, l1);
    *(uint2*)(g_sh + row*1024 + tid*4) = make_uint2(h0, h1);
    *(uint2*)(g_sl + row*1024 + tid*4) = make_uint2(l0, l1);
}

// Retrieval planes (NN): out bf16 hi/lo g_r[plane][m][e]
__global__ void __launch_bounds__(256, 3) aa_t_retr()
{
    extern __shared__ unsigned smx[];
    int t = blockIdx.z, b = t / 10, u = t % 10;
    int x = c_xy_x[u], y = c_xy_y[u];
    int bz = b*4 + x;
    int n0 = y*128 + blockIdx.x*64;
    const ushort_t* Ah = g_sh + (size_t)bz*1048576 + (size_t)blockIdx.y*128*1024;
    const ushort_t* Al = g_sl + (size_t)bz*1048576 + (size_t)blockIdx.y*128*1024;
    const ushort_t* Bh = g_vh + (size_t)b*524288 + n0;
    const ushort_t* Bl = g_vl + (size_t)b*524288 + n0;
    float acc[2][4][4] = {};
    mma_core<1>(smx, Ah, Al, 1024, Bh, Bl, 512, 1024, acc);
    size_t coff = ((size_t)(bz*4 + y))*131072 + (size_t)blockIdx.y*128*128 + blockIdx.x*64;
    epilogue_bf16(acc, g_rh + coff, g_rl + coff, 128);
}

// qk = q_plus @ Wk (NN, bias cancels in softmax) -> bf16 hi/lo
__global__ void __launch_bounds__(256, 3) aa_t_qk()
{
    extern __shared__ unsigned smx[];
    const ushort_t* Ah = g_qph + (size_t)blockIdx.y*128*128;
    const ushort_t* Al = g_qpl + (size_t)blockIdx.y*128*128;
    float acc[2][4][4] = {};
    mma_core<1>(smx, Ah, Al, 128, g_wkh + blockIdx.x*64, g_wkl + blockIdx.x*64, 128, 128, acc);
    size_t coff = (size_t)blockIdx.y*128*128 + blockIdx.x*64;
    epilogue_bf16(acc, g_qkh + coff, g_qkl + coff, 128);
}

// stage-2 scores planes (NT): g_s2[plane] = scale * qk · R^T
__global__ void __launch_bounds__(256, 3) aa_t_scores2()
{
    extern __shared__ unsigned smx[];
    int t = blockIdx.z, b = t / 10, u = t % 10;
    int x = c_xy_x[u], y = c_xy_y[u];
    size_t aoff = (size_t)b*524288 + x*128 + (size_t)blockIdx.y*128*512;
    size_t boff = ((size_t)((b*4 + x)*4 + y))*131072 + (size_t)blockIdx.x*64*128;
    float acc[2][4][4] = {};
    mma_core<0>(smx, g_qkh + aoff, g_qkl + aoff, 512, g_rh + boff, g_rl + boff, 128, 128, acc);
    float* C = g_s2 + ((size_t)(b*10 + u))*1048576
             + (size_t)blockIdx.y*128*1024 + blockIdx.x*64;
    epilogue_f32(acc, C, 1024, SCALE);
}

// softmax over y across planes -> series bf16 hi/lo (__expf)
__global__ void __launch_bounds__(256) aa_k_softmax2()
{
    int blk = blockIdx.x;
    int l = blk & 1023;
    int x = (blk >> 10) & 3;
    int b = blk >> 12;
    int ny = x + 1;
    size_t pbase = ((size_t)(b*10 + c_tri[x]))*1048576 + (size_t)l*1024 + threadIdx.x*4;
    float4 v[4];
#pragma unroll
    for (int y = 0; y < 4; y++)
        if (y < ny) v[y] = *(const float4*)(g_s2 + pbase + (size_t)y*1048576);
        else        v[y] = make_float4(-1e30f,-1e30f,-1e30f,-1e30f);
    float4 mx;
    mx.x = fmaxf(fmaxf(v[0].x,v[1].x), fmaxf(v[2].x,v[3].x));
    mx.y = fmaxf(fmaxf(v[0].y,v[1].y), fmaxf(v[2].y,v[3].y));
    mx.z = fmaxf(fmaxf(v[0].z,v[1].z), fmaxf(v[2].z,v[3].z));
    mx.w = fmaxf(fmaxf(v[0].w,v[1].w), fmaxf(v[2].w,v[3].w));
    float4 s = make_float4(0,0,0,0);
#pragma unroll
    for (int y = 0; y < 4; y++) {
        if (y < ny) {
            v[y].x = __expf(v[y].x - mx.x); s.x += v[y].x;
            v[y].y = __expf(v[y].y - mx.y); s.y += v[y].y;
            v[y].z = __expf(v[y].z - mx.z); s.z += v[y].z;
            v[y].w = __expf(v[y].w - mx.w); s.w += v[y].w;
        }
    }
    float4 inv = make_float4(1.f/s.x, 1.f/s.y, 1.f/s.z, 1.f/s.w);
#pragma unroll
    for (int y = 0; y < 4; y++) {
        if (y < ny) {
            unsigned h0,l0,h1,l1;
            split_pack(v[y].x*inv.x, v[y].y*inv.y, h0, l0);
            split_pack(v[y].z*inv.z, v[y].w*inv.w, h1, l1);
            *(uint2*)(g_s2h + pbase + (size_t)y*1048576) = make_uint2(h0, h1);
            *(uint2*)(g_s2l + pbase + (size_t)y*1048576) = make_uint2(l0, l1);
        }
    }
}

// catt partials (NN): P[plane][l][e] = series_plane @ R_plane, one plane per block-z.
__global__ void __launch_bounds__(256, 3) aa_t_catt()
{
    extern __shared__ unsigned smx[];
    int t = blockIdx.z, b = t / 10, u = t % 10;
    int x = c_xy_x[u], y = c_xy_y[u];
    size_t aoff = ((size_t)(b*10 + u))*1048576 + (size_t)blockIdx.y*128*1024;
    size_t boff = ((size_t)((b*4 + x)*4 + y))*131072 + blockIdx.x*64;
    float acc[2][4][4] = {};
    mma_core<1>(smx, g_s2h + aoff, g_s2l + aoff, 1024, g_rh + boff, g_rl + boff, 128, 1024, acc);
    float* P = g_search + (size_t)t*131072
             + (size_t)blockIdx.y*128*128 + blockIdx.x*64;
    epilogue_f32(acc, P, 128, 1.0f);
}

// reduce partials over y: g_vpart[b][l][e][x] = sum_y P[(b,x,y)][l][e]
__global__ void __launch_bounds__(256) aa_k_vred()
{
    int i = blockIdx.x * 256 + threadIdx.x;
    int e = i & 127;
    int l = (i >> 7) & 1023;
    int x = (i >> 17) & 3;
    int b = i >> 19;
    int ny = x + 1;
    size_t p0 = ((size_t)(b*10 + c_tri[x]))*131072 + (size_t)l*128 + e;
    float s = 0.f;
    for (int y = 0; y < ny; y++) s += g_search[p0 + (size_t)y*131072];
    g_vpart[(((size_t)b*1024 + l)*128 + e)*4 + x] = s;
}

// V output: g_vpart (viewed [8192,128]) @ Wv^T + bv — fp32, tiny
__global__ void __launch_bounds__(256) aa_k_vout(const float* __restrict__ Wv,
                                                 const float* __restrict__ bv,
                                                 float* __restrict__ out)
{
    gemm_nt_core(g_vpart, EE, Wv, EE, out, EE, EE, 1.0f, bv);
}

// series_out == 0.25 everywhere (float4)
__global__ void __launch_bounds__(256) aa_k_fill(float4* __restrict__ p, float v)
{
    p[(size_t)blockIdx.x * 256 + threadIdx.x] = make_float4(v, v, v, v);
}

// prior + sig (sig path bit-exact libdevice — DO NOT CHANGE; row exp -> __expf)
__global__ void __launch_bounds__(256) aa_k_prior(const float* __restrict__ sigma,
                                                  float* __restrict__ prior,
                                                  float* __restrict__ sig_out)
{
    int row = blockIdx.x;
    int i = row & 1023;
    int h = (row >> 10) & 3;
    int b = row >> 12;
    float v = sigma[((size_t)b*LL + i)*XX + h];
    float s = sig_transform(v);
    if (threadIdx.x == 0) sig_out[row] = s;
    float denom = 2.5066282746310002f * s;
    float coef = 1.0f / denom;
    float s2 = s * s;
    float* p = prior + (size_t)row * LL;
    float fi = (float)i;
    for (int j = threadIdx.x; j < LL; j += 256) {
        float d = fabsf(fi - (float)j);
        float d2 = d * d;
        float num = -d2 * 0.5f;
        float arg = num / s2;
        p[j] = coef * __expf(arg);
    }
}

// =========================================================================
extern "C" void kernel_launch(void* const* d_in, const int* in_sizes, int n_in,
                              void* d_out, int out_size)
{
    const float* big[5] = {};
    int nbig = 0;
    const float* sigma = nullptr;
    const float* w[2] = {};
    int nw = 0;
    const float* bias[2] = {};
    int nb = 0;
    for (int i = 0; i < n_in; i++) {
        int sz = in_sizes[i];
        if (sz == BB*LL*XX*EE)      { if (nbig < 5) big[nbig++] = (const float*)d_in[i]; }
        else if (sz == BB*LL*XX)    { sigma = (const float*)d_in[i]; }
        else if (sz == EE*EE)       { if (nw < 2) w[nw++] = (const float*)d_in[i]; }
        else if (sz == EE)          { if (nb < 2) bias[nb++] = (const float*)d_in[i]; }
    }
    const float* query = big[1];
    const float* key_  = big[2];
    const float* value = big[3];
    const float* qplus = big[4];
    const float* Wk = w[0];
    const float* Wv = w[1];    const float* bv = bias[1];

    float* out       = (float*)d_out;
    float* outV      = out;
    float* outSeries = out + 1048576;
    float* outPrior  = out + 1048576 + 8388608;
    float* outSig    = out + 1048576 + 2*8388608;

    static int smem_set = 0;
    if (!smem_set) {
        cudaFuncSetAttribute(aa_t_scores1, cudaFuncAttributeMaxDynamicSharedMemorySize, SMEM_MMA);
        cudaFuncSetAttribute(aa_t_retr,    cudaFuncAttributeMaxDynamicSharedMemorySize, SMEM_MMA);
        cudaFuncSetAttribute(aa_t_qk,      cudaFuncAttributeMaxDynamicSharedMemorySize, SMEM_MMA);
        cudaFuncSetAttribute(aa_t_scores2, cudaFuncAttributeMaxDynamicSharedMemorySize, SMEM_MMA);
        cudaFuncSetAttribute(aa_t_catt,    cudaFuncAttributeMaxDynamicSharedMemorySize, SMEM_MMA);
        cudaFuncSetAttribute(aa_t_scores1, cudaFuncAttributePreferredSharedMemoryCarveout, 100);
        cudaFuncSetAttribute(aa_t_retr,    cudaFuncAttributePreferredSharedMemoryCarveout, 100);
        cudaFuncSetAttribute(aa_t_qk,      cudaFuncAttributePreferredSharedMemoryCarveout, 100);
        cudaFuncSetAttribute(aa_t_scores2, cudaFuncAttributePreferredSharedMemoryCarveout, 100);
        cudaFuncSetAttribute(aa_t_catt,    cudaFuncAttributePreferredSharedMemoryCarveout, 100);
        smem_set = 1;
    }

    dim3 thr(256);
    aa_cvt      <<<dim3(1024,5),   thr>>>(query, key_, value, qplus, Wk);
    aa_t_scores1<<<dim3(16,8,8),   thr, SMEM_MMA>>>();
    aa_k_softmax<<<dim3(8192),     thr>>>();
    aa_t_retr   <<<dim3(2,8,20),   thr, SMEM_MMA>>>();
    aa_t_qk     <<<dim3(2,64),     thr, SMEM_MMA>>>();
    aa_t_scores2<<<dim3(16,8,20),  thr, SMEM_MMA>>>();
    aa_k_softmax2<<<dim3(8192),    thr>>>();
    aa_t_catt   <<<dim3(2,8,20),   thr, SMEM_MMA>>>();
    aa_k_vred   <<<dim3(4096),     thr>>>();
    aa_k_vout   <<<dim3(2,128),    thr>>>(Wv, bv, outV);
    aa_k_fill   <<<dim3(8192),     thr>>>((float4*)outSeries, 0.25f);
    aa_k_prior  <<<dim3(8192),     thr>>>(sigma, outPrior, outSig);
}

// round 17
// speedup vs baseline: 1.2246x; 1.0256x over previous
#include <cuda_runtime.h>
#include <math.h>

#define BB 2
#define LL 1024
#define XX 4
#define EE 128
#define YY 4
#define SCALE 0.08838834764831845f   // 1/sqrt(128)

typedef unsigned short ushort_t;

// ---------------- scratch (static device globals) --------------------------
__device__ float g_search[8*1024*1024];                 // stage1 scores fp32; reused as catt partials
__device__ float g_s2    [2*10*1024*1024];              // stage2 scores fp32  80 MB
__device__ float g_vpart [BB*LL*EE*XX];                 // [b][l][e][x]         4 MB

__device__ __align__(16) ushort_t g_qh [2*1024*4*128], g_ql [2*1024*4*128];
__device__ __align__(16) ushort_t g_kh [2*1024*4*128], g_kl [2*1024*4*128];
__device__ __align__(16) ushort_t g_vh [2*1024*512],   g_vl [2*1024*512];
__device__ __align__(16) ushort_t g_qph[2*1024*4*128], g_qpl[2*1024*4*128];
__device__ __align__(16) ushort_t g_wkh[128*128],      g_wkl[128*128];
__device__ __align__(16) ushort_t g_sh [8*1024*1024],  g_sl [8*1024*1024];   // Search bf16
__device__ __align__(16) ushort_t g_qkh[2*1024*4*128], g_qkl[2*1024*4*128];
__device__ __align__(16) ushort_t g_rh [2*4*4*1024*128], g_rl[2*4*4*1024*128];
__device__ __align__(16) ushort_t g_s2h[2*10*1024*1024], g_s2l[2*10*1024*1024];

__constant__ int c_xy_x[10] = {0,1,1,2,2,2,3,3,3,3};
__constant__ int c_xy_y[10] = {0,0,1,0,1,2,0,1,2,3};
__constant__ int c_tri[4]  = {0,1,3,6};

// libdevice path — bit-matches jax-on-GPU reference. DO NOT CHANGE.
__device__ __forceinline__ float sig_transform(float v) {
    float t = 5.0f * v;
    float e = expf(-t);
    float sigmoid = 1.0f / (1.0f + e);
    float sg = sigmoid + 1e-5f;
    float p = powf(3.0f, sg);
    return p - 1.0f;
}

// ================= bf16 split helpers =======================================
__device__ __forceinline__ unsigned bfbits(float x) {
    unsigned u = __float_as_uint(x);
    return (u + 0x7fffu + ((u >> 16) & 1u)) >> 16;
}
__device__ __forceinline__ float bfval(unsigned b) { return __uint_as_float(b << 16); }
__device__ __forceinline__ void split_pack(float x0, float x1, unsigned &hi, unsigned &lo) {
    unsigned h0 = bfbits(x0), h1 = bfbits(x1);
    unsigned l0 = bfbits(x0 - bfval(h0)), l1 = bfbits(x1 - bfval(h1));
    hi = h0 | (h1 << 16);
    lo = l0 | (l1 << 16);
}
__device__ __forceinline__ void mma_bf16(float (&c)[4],
    unsigned a0, unsigned a1, unsigned a2, unsigned a3,
    unsigned b0, unsigned b1)
{
    asm volatile("mma.sync.aligned.m16n8k16.row.col.f32.bf16.bf16.f32 "
        "{%0,%1,%2,%3},{%4,%5,%6,%7},{%8,%9},{%0,%1,%2,%3};"
        : "+f"(c[0]), "+f"(c[1]), "+f"(c[2]), "+f"(c[3])
        : "r"(a0), "r"(a1), "r"(a2), "r"(a3), "r"(b0), "r"(b1));
}
__device__ __forceinline__ void ldsm_x4(unsigned &r0, unsigned &r1,
                                        unsigned &r2, unsigned &r3, unsigned addr)
{
    asm volatile("ldmatrix.sync.aligned.m8n8.x4.shared.b16 {%0,%1,%2,%3}, [%4];"
        : "=r"(r0), "=r"(r1), "=r"(r2), "=r"(r3) : "r"(addr));
}
__device__ __forceinline__ void ldsm_x4t(unsigned &r0, unsigned &r1,
                                         unsigned &r2, unsigned &r3, unsigned addr)
{
    asm volatile("ldmatrix.sync.aligned.m8n8.x4.trans.shared.b16 {%0,%1,%2,%3}, [%4];"
        : "=r"(r0), "=r"(r1), "=r"(r2), "=r"(r3) : "r"(addr));
}
__device__ __forceinline__ void cp_async16(void* dst, const void* src) {
    unsigned s = (unsigned)__cvta_generic_to_shared(dst);
    asm volatile("cp.async.cg.shared.global [%0], [%1], 16;" :: "r"(s), "l"(src));
}
#define CP_COMMIT() asm volatile("cp.async.commit_group;")
template<int N>
__device__ __forceinline__ void cp_wait() {
    asm volatile("cp.async.wait_group %0;" :: "n"(N));
}

// C tile 128x64, 256 threads (8 warps = 4x2 grid of 32x32 warp tiles).
// Operands pre-split bf16 hi/lo in gmem; lda/ldb in bf16 elements.
// TRANSB=0: B is [n][k] (NT). TRANSB=1: B is [k][n] (NN, via ldmatrix.trans).
// 2-stage cp.async double buffer (dynamic smem, 2 * 30 KB).
template<int TRANSB>
__device__ __forceinline__ void mma_core(
    unsigned* __restrict__ SM_,
    const ushort_t* __restrict__ Ahg, const ushort_t* __restrict__ Alg, int lda,
    const ushort_t* __restrict__ Bhg, const ushort_t* __restrict__ Blg, int ldb,
    int K, float (&acc)[2][4][4])
{
    const int tid = threadIdx.x;
    const int lane = tid & 31, w = tid >> 5;
    const int wrow = w >> 1, wcol = w & 1;
    const int lm = lane & 15, lq = lane >> 4;

    const int ar = tid >> 1, ax = tid & 1;    // A staging: 2 thr/row, 16 ushort each
    const int br = tid >> 2, bq = tid & 3;    // B NT: 4 thr/row, 8 ushort each
    const int half = tid >> 7, t7 = tid & 127;
    const int nr = t7 >> 2, nq = t7 & 3;      // B NN: per plane-half, 16 ushort each

    auto prefetch = [&](int kk, int s) {
        unsigned* SA = SM_ + s * 7680;
        unsigned* SB = SA + 5120;
        const ushort_t* pa = Ahg + (size_t)ar*lda + kk + ax*16;
        const ushort_t* pl = Alg + (size_t)ar*lda + kk + ax*16;
        cp_async16(&SA[ar*20 + ax*8],            pa);
        cp_async16(&SA[ar*20 + ax*8 + 4],        pa + 8);
        cp_async16(&SA[2560 + ar*20 + ax*8],     pl);
        cp_async16(&SA[2560 + ar*20 + ax*8 + 4], pl + 8);
        if (TRANSB) {
            const ushort_t* pb = (half ? Blg : Bhg) + (size_t)(kk + nr)*ldb + nq*16;
            ushort_t* bd = (ushort_t*)(SB + half*1280) + nr*72 + nq*16;
            cp_async16(bd,     pb);
            cp_async16(bd + 8, pb + 8);
        } else {
            cp_async16(&SB[br*20 + bq*4],        Bhg + (size_t)br*ldb + kk + bq*8);
            cp_async16(&SB[1280 + br*20 + bq*4], Blg + (size_t)br*ldb + kk + bq*8);
        }
    };

    const int nck = K >> 5;
    prefetch(0, 0); CP_COMMIT();
    for (int c = 0; c < nck; c++) {
        if (c + 1 < nck) { prefetch((c+1) << 5, (c+1) & 1); CP_COMMIT(); cp_wait<1>(); }
        else             { cp_wait<0>(); }
        __syncthreads();
        unsigned* SA = SM_ + (c & 1) * 7680;
        unsigned* SB = SA + 5120;
#pragma unroll
        for (int k16 = 0; k16 < 2; k16++) {
            const int ko = k16*8;
            unsigned ah[2][4], al[2][4], bh[4][2], bl[4][2];
#pragma unroll
            for (int mt = 0; mt < 2; mt++) {
                int m = wrow*32 + mt*16;
                unsigned aw = (unsigned)__cvta_generic_to_shared(
                    &SA[(m + lm)*20 + ko + (lq<<2)]);
                ldsm_x4(ah[mt][0], ah[mt][1], ah[mt][2], ah[mt][3], aw);
                ldsm_x4(al[mt][0], al[mt][1], al[mt][2], al[mt][3], aw + 2560*4);
            }
#pragma unroll
            for (int p = 0; p < 2; p++) {
                int n0 = wcol*32 + p*16;
                if (TRANSB) {
                    const ushort_t* bb = (const ushort_t*)SB;
                    unsigned bw = (unsigned)__cvta_generic_to_shared(
                        bb + (k16*16 + lm)*72 + n0 + (lq<<3));
                    ldsm_x4t(bh[2*p][0], bh[2*p][1], bh[2*p+1][0], bh[2*p+1][1], bw);
                    ldsm_x4t(bl[2*p][0], bl[2*p][1], bl[2*p+1][0], bl[2*p+1][1], bw + 1280*4);
                } else {
                    unsigned bw = (unsigned)__cvta_generic_to_shared(
                        &SB[(n0 + lm)*20 + ko + (lq<<2)]);
                    ldsm_x4(bh[2*p][0], bh[2*p+1][0], bh[2*p][1], bh[2*p+1][1], bw);
                    ldsm_x4(bl[2*p][0], bl[2*p+1][0], bl[2*p][1], bl[2*p+1][1], bw + 1280*4);
                }
            }
#pragma unroll
            for (int mt = 0; mt < 2; mt++)
#pragma unroll
                for (int nt = 0; nt < 4; nt++) {
                    mma_bf16(acc[mt][nt], ah[mt][0],ah[mt][1],ah[mt][2],ah[mt][3], bh[nt][0],bh[nt][1]);
                    mma_bf16(acc[mt][nt], ah[mt][0],ah[mt][1],ah[mt][2],ah[mt][3], bl[nt][0],bl[nt][1]);
                    mma_bf16(acc[mt][nt], al[mt][0],al[mt][1],al[mt][2],al[mt][3], bh[nt][0],bh[nt][1]);
                }
        }
        __syncthreads();
    }
}

#define SMEM_MMA (2*7680*4)   // 61440 bytes

__device__ __forceinline__ void epilogue_f32(
    float (&acc)[2][4][4], float* C, int ldc, float scale)
{
    const int lane = threadIdx.x & 31, w = threadIdx.x >> 5;
    const int g = lane >> 2, tg = lane & 3;
    const int wrow = w >> 1, wcol = w & 1;
#pragma unroll
    for (int mt = 0; mt < 2; mt++)
#pragma unroll
        for (int nt = 0; nt < 4; nt++) {
            int r0 = wrow*32 + mt*16 + g;
            int c0 = wcol*32 + nt*8 + 2*tg;
            float2 v0 = {acc[mt][nt][0]*scale, acc[mt][nt][1]*scale};
            float2 v1 = {acc[mt][nt][2]*scale, acc[mt][nt][3]*scale};
            *(float2*)(C + (size_t)r0*ldc + c0) = v0;
            *(float2*)(C + (size_t)(r0+8)*ldc + c0) = v1;
        }
}

__device__ __forceinline__ void epilogue_bf16(
    float (&acc)[2][4][4], ushort_t* Ch, ushort_t* Cl, int ldc)
{
    const int lane = threadIdx.x & 31, w = threadIdx.x >> 5;
    const int g = lane >> 2, tg = lane & 3;
    const int wrow = w >> 1, wcol = w & 1;
#pragma unroll
    for (int mt = 0; mt < 2; mt++)
#pragma unroll
        for (int nt = 0; nt < 4; nt++) {
            int r0 = wrow*32 + mt*16 + g;
            int c0 = wcol*32 + nt*8 + 2*tg;
            unsigned h, l;
            split_pack(acc[mt][nt][0], acc[mt][nt][1], h, l);
            *(unsigned*)(Ch + (size_t)r0*ldc + c0) = h;
            *(unsigned*)(Cl + (size_t)r0*ldc + c0) = l;
            split_pack(acc[mt][nt][2], acc[mt][nt][3], h, l);
            *(unsigned*)(Ch + (size_t)(r0+8)*ldc + c0) = h;
            *(unsigned*)(Cl + (size_t)(r0+8)*ldc + c0) = l;
        }
}

// ---------------- fp32 NT core (vout only) ---------------------------------
__device__ __forceinline__ void gemm_nt_core(
    const float* __restrict__ A, int lda,
    const float* __restrict__ B, int ldb,
    float* __restrict__ C, int ldc,
    int K, float scale, const float* __restrict__ bias)
{
    __shared__ float As[16*68];
    __shared__ float Bs[16*68];
    const int tid = threadIdx.x;
    const int tx = tid & 15, ty = tid >> 4;
    const int lr = tid >> 2;
    const int lk = (tid & 3) << 2;
    const int row0 = blockIdx.y * 64;
    const int col0 = blockIdx.x * 64;
    const float* Ap = A + (size_t)(row0 + lr) * lda + lk;
    const float* Bp = B + (size_t)(col0 + lr) * ldb + lk;
    float acc[4][4] = {};
    for (int kk = 0; kk < K; kk += 16) {
        float4 av = *(const float4*)(Ap + kk);
        float4 bv = *(const float4*)(Bp + kk);
        __syncthreads();
        As[(lk+0)*68+lr]=av.x; As[(lk+1)*68+lr]=av.y;
        As[(lk+2)*68+lr]=av.z; As[(lk+3)*68+lr]=av.w;
        Bs[(lk+0)*68+lr]=bv.x; Bs[(lk+1)*68+lr]=bv.y;
        Bs[(lk+2)*68+lr]=bv.z; Bs[(lk+3)*68+lr]=bv.w;
        __syncthreads();
#pragma unroll
        for (int k = 0; k < 16; k++) {
            float4 a4 = *(const float4*)&As[k*68 + ty*4];
            float4 b4 = *(const float4*)&Bs[k*68 + tx*4];
            float a_[4] = {a4.x, a4.y, a4.z, a4.w};
            float b_[4] = {b4.x, b4.y, b4.z, b4.w};
#pragma unroll
            for (int i = 0; i < 4; i++)
#pragma unroll
                for (int j = 0; j < 4; j++)
                    acc[i][j] = fmaf(a_[i], b_[j], acc[i][j]);
        }
    }
#pragma unroll
    for (int i = 0; i < 4; i++) {
        float4 o;
        o.x = acc[i][0]*scale + bias[col0+tx*4+0];
        o.y = acc[i][1]*scale + bias[col0+tx*4+1];
        o.z = acc[i][2]*scale + bias[col0+tx*4+2];
        o.w = acc[i][3]*scale + bias[col0+tx*4+3];
        *(float4*)&C[(size_t)(row0+ty*4+i)*ldc + col0 + tx*4] = o;
    }
}

// ================= kernels ==================================================

// split fp32 inputs -> bf16 hi/lo
__global__ void __launch_bounds__(256) aa_cvt(
    const float* __restrict__ q, const float* __restrict__ k,
    const float* __restrict__ val, const float* __restrict__ qp,
    const float* __restrict__ Wk)
{
    const float* src; ushort_t *dh, *dl; int n;
    switch (blockIdx.y) {
        case 0: src = q;   dh = g_qh;  dl = g_ql;  n = 1048576; break;
        case 1: src = k;   dh = g_kh;  dl = g_kl;  n = 1048576; break;
        case 2: src = val; dh = g_vh;  dl = g_vl;  n = 1048576; break;
        case 3: src = qp;  dh = g_qph; dl = g_qpl; n = 1048576; break;
        default:src = Wk;  dh = g_wkh; dl = g_wkl; n = 16384;   break;
    }
    int i = (blockIdx.x * 256 + threadIdx.x) * 4;
    if (i >= n) return;
    float4 v = *(const float4*)(src + i);
    unsigned h0,l0,h1,l1;
    split_pack(v.x, v.y, h0, l0);
    split_pack(v.z, v.w, h1, l1);
    *(uint2*)(dh + i) = make_uint2(h0, h1);
    *(uint2*)(dl + i) = make_uint2(l0, l1);
}

// stage 1 scores: g_search = scale * Q K^T
__global__ void __launch_bounds__(256, 3) aa_t_scores1()
{
    extern __shared__ unsigned smx[];
    int bz = blockIdx.z, b = bz >> 2, x = bz & 3;
    size_t qoff = (size_t)b*524288 + x*128;
    const ushort_t* Ah = g_qh + qoff + (size_t)blockIdx.y*128*512;
    const ushort_t* Al = g_ql + qoff + (size_t)blockIdx.y*128*512;
    const ushort_t* Bh = g_kh + qoff + (size_t)blockIdx.x*64*512;
    const ushort_t* Bl = g_kl + qoff + (size_t)blockIdx.x*64*512;
    float acc[2][4][4] = {};
    mma_core<0>(smx, Ah, Al, 512, Bh, Bl, 512, 128, acc);
    float* C = g_search + (size_t)bz*1048576 + (size_t)blockIdx.y*128*1024 + blockIdx.x*64;
    epilogue_f32(acc, C, 1024, SCALE);
}

// row softmax over s; emits bf16 hi/lo Search (shuffle reduction + __expf)
__global__ void __launch_bounds__(256) aa_k_softmax()
{
    size_t row = blockIdx.x;
    const float* p = g_search + row * 1024;
    int tid = threadIdx.x;
    int lane = tid & 31, wid = tid >> 5;
    float4 v4 = *(const float4*)(p + tid*4);
    float v[4] = {v4.x, v4.y, v4.z, v4.w};
    float m = fmaxf(fmaxf(v[0], v[1]), fmaxf(v[2], v[3]));
#pragma unroll
    for (int o = 16; o > 0; o >>= 1) m = fmaxf(m, __shfl_xor_sync(~0u, m, o));
    __shared__ float red[8];
    if (lane == 0) red[wid] = m;
    __syncthreads();
    m = red[0];
#pragma unroll
    for (int i = 1; i < 8; i++) m = fmaxf(m, red[i]);
    float sum = 0.f;
#pragma unroll
    for (int i = 0; i < 4; i++) { v[i] = __expf(v[i] - m); sum += v[i]; }
#pragma unroll
    for (int o = 16; o > 0; o >>= 1) sum += __shfl_xor_sync(~0u, sum, o);
    __syncthreads();
    if (lane == 0) red[wid] = sum;
    __syncthreads();
    sum = red[0];
#pragma unroll
    for (int i = 1; i < 8; i++) sum += red[i];
    float inv = 1.f / sum;
    unsigned h0,l0,h1,l1;
    split_pack(v[0]*inv, v[1]*inv, h0, l0);
    split_pack(v[2]*inv, v[3]*inv, h1, l1);
    *(uint2*)(g_sh + row*1024 + tid*4) = make_uint2(h0, h1);
    *(uint2*)(g_sl + row*1024 + tid*4) = make_uint2(l0, l1);
}

// Retrieval planes (NN): out bf16 hi/lo g_r[plane][m][e]
__global__ void __launch_bounds__(256, 3) aa_t_retr()
{
    extern __shared__ unsigned smx[];
    int t = blockIdx.z, b = t / 10, u = t % 10;
    int x = c_xy_x[u], y = c_xy_y[u];
    int bz = b*4 + x;
    int n0 = y*128 + blockIdx.x*64;
    const ushort_t* Ah = g_sh + (size_t)bz*1048576 + (size_t)blockIdx.y*128*1024;
    const ushort_t* Al = g_sl + (size_t)bz*1048576 + (size_t)blockIdx.y*128*1024;
    const ushort_t* Bh = g_vh + (size_t)b*524288 + n0;
    const ushort_t* Bl = g_vl + (size_t)b*524288 + n0;
    float acc[2][4][4] = {};
    mma_core<1>(smx, Ah, Al, 1024, Bh, Bl, 512, 1024, acc);
    size_t coff = ((size_t)(bz*4 + y))*131072 + (size_t)blockIdx.y*128*128 + blockIdx.x*64;
    epilogue_bf16(acc, g_rh + coff, g_rl + coff, 128);
}

// qk = q_plus @ Wk (NN, bias cancels in softmax) -> bf16 hi/lo
__global__ void __launch_bounds__(256, 3) aa_t_qk()
{
    extern __shared__ unsigned smx[];
    const ushort_t* Ah = g_qph + (size_t)blockIdx.y*128*128;
    const ushort_t* Al = g_qpl + (size_t)blockIdx.y*128*128;
    float acc[2][4][4] = {};
    mma_core<1>(smx, Ah, Al, 128, g_wkh + blockIdx.x*64, g_wkl + blockIdx.x*64, 128, 128, acc);
    size_t coff = (size_t)blockIdx.y*128*128 + blockIdx.x*64;
    epilogue_bf16(acc, g_qkh + coff, g_qkl + coff, 128);
}

// stage-2 scores planes (NT): g_s2[plane] = scale * qk · R^T
__global__ void __launch_bounds__(256, 3) aa_t_scores2()
{
    extern __shared__ unsigned smx[];
    int t = blockIdx.z, b = t / 10, u = t % 10;
    int x = c_xy_x[u], y = c_xy_y[u];
    size_t aoff = (size_t)b*524288 + x*128 + (size_t)blockIdx.y*128*512;
    size_t boff = ((size_t)((b*4 + x)*4 + y))*131072 + (size_t)blockIdx.x*64*128;
    float acc[2][4][4] = {};
    mma_core<0>(smx, g_qkh + aoff, g_qkl + aoff, 512, g_rh + boff, g_rl + boff, 128, 128, acc);
    float* C = g_s2 + ((size_t)(b*10 + u))*1048576
             + (size_t)blockIdx.y*128*1024 + blockIdx.x*64;
    epilogue_f32(acc, C, 1024, SCALE);
}

// softmax over y across planes -> series bf16 hi/lo (__expf)
__global__ void __launch_bounds__(256) aa_k_softmax2()
{
    int blk = blockIdx.x;
    int l = blk & 1023;
    int x = (blk >> 10) & 3;
    int b = blk >> 12;
    int ny = x + 1;
    size_t pbase = ((size_t)(b*10 + c_tri[x]))*1048576 + (size_t)l*1024 + threadIdx.x*4;
    float4 v[4];
#pragma unroll
    for (int y = 0; y < 4; y++)
        if (y < ny) v[y] = *(const float4*)(g_s2 + pbase + (size_t)y*1048576);
        else        v[y] = make_float4(-1e30f,-1e30f,-1e30f,-1e30f);
    float4 mx;
    mx.x = fmaxf(fmaxf(v[0].x,v[1].x), fmaxf(v[2].x,v[3].x));
    mx.y = fmaxf(fmaxf(v[0].y,v[1].y), fmaxf(v[2].y,v[3].y));
    mx.z = fmaxf(fmaxf(v[0].z,v[1].z), fmaxf(v[2].z,v[3].z));
    mx.w = fmaxf(fmaxf(v[0].w,v[1].w), fmaxf(v[2].w,v[3].w));
    float4 s = make_float4(0,0,0,0);
#pragma unroll
    for (int y = 0; y < 4; y++) {
        if (y < ny) {
            v[y].x = __expf(v[y].x - mx.x); s.x += v[y].x;
            v[y].y = __expf(v[y].y - mx.y); s.y += v[y].y;
            v[y].z = __expf(v[y].z - mx.z); s.z += v[y].z;
            v[y].w = __expf(v[y].w - mx.w); s.w += v[y].w;
        }
    }
    float4 inv = make_float4(1.f/s.x, 1.f/s.y, 1.f/s.z, 1.f/s.w);
#pragma unroll
    for (int y = 0; y < 4; y++) {
        if (y < ny) {
            unsigned h0,l0,h1,l1;
            split_pack(v[y].x*inv.x, v[y].y*inv.y, h0, l0);
            split_pack(v[y].z*inv.z, v[y].w*inv.w, h1, l1);
            *(uint2*)(g_s2h + pbase + (size_t)y*1048576) = make_uint2(h0, h1);
            *(uint2*)(g_s2l + pbase + (size_t)y*1048576) = make_uint2(l0, l1);
        }
    }
}

// catt partials (NN): P[plane][l][e] = series_plane @ R_plane, one plane per block-z.
__global__ void __launch_bounds__(256, 3) aa_t_catt()
{
    extern __shared__ unsigned smx[];
    int t = blockIdx.z, b = t / 10, u = t % 10;
    int x = c_xy_x[u], y = c_xy_y[u];
    size_t aoff = ((size_t)(b*10 + u))*1048576 + (size_t)blockIdx.y*128*1024;
    size_t boff = ((size_t)((b*4 + x)*4 + y))*131072 + blockIdx.x*64;
    float acc[2][4][4] = {};
    mma_core<1>(smx, g_s2h + aoff, g_s2l + aoff, 1024, g_rh + boff, g_rl + boff, 128, 1024, acc);
    float* P = g_search + (size_t)t*131072
             + (size_t)blockIdx.y*128*128 + blockIdx.x*64;
    epilogue_f32(acc, P, 128, 1.0f);
}

// reduce partials over y: g_vpart[b][l][e][x] = sum_y P[(b,x,y)][l][e]
__global__ void __launch_bounds__(256) aa_k_vred()
{
    int i = blockIdx.x * 256 + threadIdx.x;
    int e = i & 127;
    int l = (i >> 7) & 1023;
    int x = (i >> 17) & 3;
    int b = i >> 19;
    int ny = x + 1;
    size_t p0 = ((size_t)(b*10 + c_tri[x]))*131072 + (size_t)l*128 + e;
    float s = 0.f;
    for (int y = 0; y < ny; y++) s += g_search[p0 + (size_t)y*131072];
    g_vpart[(((size_t)b*1024 + l)*128 + e)*4 + x] = s;
}

// V output: g_vpart (viewed [8192,128]) @ Wv^T + bv — fp32, tiny
__global__ void __launch_bounds__(256) aa_k_vout(const float* __restrict__ Wv,
                                                 const float* __restrict__ bv,
                                                 float* __restrict__ out)
{
    gemm_nt_core(g_vpart, EE, Wv, EE, out, EE, EE, 1.0f, bv);
}

// series_out == 0.25 everywhere (float4)
__global__ void __launch_bounds__(256) aa_k_fill(float4* __restrict__ p, float v)
{
    p[(size_t)blockIdx.x * 256 + threadIdx.x] = make_float4(v, v, v, v);
}

// prior + sig (sig path bit-exact libdevice — DO NOT CHANGE; row exp -> __expf)
__global__ void __launch_bounds__(256) aa_k_prior(const float* __restrict__ sigma,
                                                  float* __restrict__ prior,
                                                  float* __restrict__ sig_out)
{
    int row = blockIdx.x;
    int i = row & 1023;
    int h = (row >> 10) & 3;
    int b = row >> 12;
    float v = sigma[((size_t)b*LL + i)*XX + h];
    float s = sig_transform(v);
    if (threadIdx.x == 0) sig_out[row] = s;
    float denom = 2.5066282746310002f * s;
    float coef = 1.0f / denom;
    float s2 = s * s;
    float* p = prior + (size_t)row * LL;
    float fi = (float)i;
    for (int j = threadIdx.x; j < LL; j += 256) {
        float d = fabsf(fi - (float)j);
        float d2 = d * d;
        float num = -d2 * 0.5f;
        float arg = num / s2;
        p[j] = coef * __expf(arg);
    }
}

// =========================================================================
extern "C" void kernel_launch(void* const* d_in, const int* in_sizes, int n_in,
                              void* d_out, int out_size)
{
    const float* big[5] = {};
    int nbig = 0;
    const float* sigma = nullptr;
    const float* w[2] = {};
    int nw = 0;
    const float* bias[2] = {};
    int nb = 0;
    for (int i = 0; i < n_in; i++) {
        int sz = in_sizes[i];
        if (sz == BB*LL*XX*EE)      { if (nbig < 5) big[nbig++] = (const float*)d_in[i]; }
        else if (sz == BB*LL*XX)    { sigma = (const float*)d_in[i]; }
        else if (sz == EE*EE)       { if (nw < 2) w[nw++] = (const float*)d_in[i]; }
        else if (sz == EE)          { if (nb < 2) bias[nb++] = (const float*)d_in[i]; }
    }
    const float* query = big[1];
    const float* key_  = big[2];
    const float* value = big[3];
    const float* qplus = big[4];
    const float* Wk = w[0];
    const float* Wv = w[1];    const float* bv = bias[1];

    float* out       = (float*)d_out;
    float* outV      = out;
    float* outSeries = out + 1048576;
    float* outPrior  = out + 1048576 + 8388608;
    float* outSig    = out + 1048576 + 2*8388608;

    static int init_done = 0;
    static cudaStream_t s_aux = nullptr, s_qk = nullptr;
    static cudaEvent_t ev_fork = nullptr, ev_cvt = nullptr,
                       ev_aux = nullptr, ev_qk = nullptr;
    if (!init_done) {
        cudaFuncSetAttribute(aa_t_scores1, cudaFuncAttributeMaxDynamicSharedMemorySize, SMEM_MMA);
        cudaFuncSetAttribute(aa_t_retr,    cudaFuncAttributeMaxDynamicSharedMemorySize, SMEM_MMA);
        cudaFuncSetAttribute(aa_t_qk,      cudaFuncAttributeMaxDynamicSharedMemorySize, SMEM_MMA);
        cudaFuncSetAttribute(aa_t_scores2, cudaFuncAttributeMaxDynamicSharedMemorySize, SMEM_MMA);
        cudaFuncSetAttribute(aa_t_catt,    cudaFuncAttributeMaxDynamicSharedMemorySize, SMEM_MMA);
        cudaStreamCreateWithFlags(&s_aux, cudaStreamNonBlocking);
        cudaStreamCreateWithFlags(&s_qk,  cudaStreamNonBlocking);
        cudaEventCreateWithFlags(&ev_fork, cudaEventDisableTiming);
        cudaEventCreateWithFlags(&ev_cvt,  cudaEventDisableTiming);
        cudaEventCreateWithFlags(&ev_aux,  cudaEventDisableTiming);
        cudaEventCreateWithFlags(&ev_qk,   cudaEventDisableTiming);
        init_done = 1;
    }

    dim3 thr(256);

    // ---- fork side branch: fill + prior depend only on kernel inputs ----
    cudaEventRecord(ev_fork, 0);
    cudaStreamWaitEvent(s_aux, ev_fork, 0);
    aa_k_fill <<<dim3(8192), thr, 0, s_aux>>>((float4*)outSeries, 0.25f);
    aa_k_prior<<<dim3(8192), thr, 0, s_aux>>>(sigma, outPrior, outSig);
    cudaEventRecord(ev_aux, s_aux);

    // ---- main chain ----
    aa_cvt<<<dim3(1024,5), thr>>>(query, key_, value, qplus, Wk);
    cudaEventRecord(ev_cvt, 0);

    // ---- qk branch (needs only cvt) ----
    cudaStreamWaitEvent(s_qk, ev_cvt, 0);
    aa_t_qk<<<dim3(2,64), thr, SMEM_MMA, s_qk>>>();
    cudaEventRecord(ev_qk, s_qk);

    aa_t_scores1<<<dim3(16,8,8),  thr, SMEM_MMA>>>();
    aa_k_softmax<<<dim3(8192),    thr>>>();
    aa_t_retr   <<<dim3(2,8,20),  thr, SMEM_MMA>>>();

    cudaStreamWaitEvent(0, ev_qk, 0);   // scores2 needs qk
    aa_t_scores2<<<dim3(16,8,20), thr, SMEM_MMA>>>();
    aa_k_softmax2<<<dim3(8192),   thr>>>();
    aa_t_catt   <<<dim3(2,8,20),  thr, SMEM_MMA>>>();
    aa_k_vred   <<<dim3(4096),    thr>>>();
    aa_k_vout   <<<dim3(2,128),   thr>>>(Wv, bv, outV);

    cudaStreamWaitEvent(0, ev_aux, 0);  // join side branch
}